// round 8
// baseline (speedup 1.0000x reference)
#include <cuda_runtime.h>
#include <cuda_bf16.h>
#include <cstdint>

#define T_DIM 256
#define B_DIM 256
#define H_DIM 512
#define K_DIM 64
#define M_DIM (T_DIM * B_DIM)

// Scratch (device globals; no allocations anywhere)
__device__ float g_em[(size_t)M_DIM * K_DIM];   // emissions [T,B,K] f32
__device__ float g_diff[B_DIM];                 // per-batch forward - gold
__device__ unsigned int g_cnt = 0;              // last-block counter (self-resetting)

__device__ __forceinline__ uint32_t f2bf2(float lo, float hi) {
    uint32_t r;
    asm("cvt.rn.bf16x2.f32 %0, %1, %2;" : "=r"(r) : "f"(hi), "f"(lo));
    return r;
}

// ---------------------------------------------------------------------------
// Kernel 1: emissions GEMM  (unchanged; 54.0us measured)
// ---------------------------------------------------------------------------
extern __shared__ unsigned long long sB[];   // 8192 u64 = 64 KB dynamic

__global__ __launch_bounds__(256, 2) void emis_gemm(const float* __restrict__ hid,
                                                    const float* __restrict__ W,
                                                    const float* __restrict__ bias) {
    int tid = threadIdx.x;

    for (int i = tid; i < (K_DIM * H_DIM) / 4; i += 256) {
        int n  = i >> 7;
        int r  = i & 127;
        int kk = r >> 2;
        int tg = r & 3;
        const float2* src = (const float2*)(W + n * H_DIM + kk * 16 + tg * 2);
        float2 lo = src[0];
        float2 hi = src[4];
        uint32_t wl = f2bf2(lo.x, lo.y);
        uint32_t wh = f2bf2(hi.x, hi.y);
        unsigned long long u;
        asm("mov.b64 %0, {%1,%2};" : "=l"(u) : "r"(wl), "r"(wh));
        int g = n & 7, nt = n >> 3;
        int p = nt >> 1, half = nt & 1;
        sB[(kk * 4 + tg) * 64 + (p * 8 + (g ^ (tg << 1))) * 2 + half] = u;
    }
    __syncthreads();

    int warp = tid >> 5;
    int lane = tid & 31;
    int g  = lane >> 2;
    int tg = lane & 3;
    int row0 = blockIdx.x * 256 + warp * 32;

    const float* a0p = hid + (size_t)(row0 + g)      * H_DIM + tg * 2;
    const float* a1p = hid + (size_t)(row0 + g + 8)  * H_DIM + tg * 2;
    const float* a2p = hid + (size_t)(row0 + g + 16) * H_DIM + tg * 2;
    const float* a3p = hid + (size_t)(row0 + g + 24) * H_DIM + tg * 2;

    float acc[16][4];
#pragma unroll
    for (int nt = 0; nt < 16; nt++)
#pragma unroll
        for (int q = 0; q < 4; q++) acc[nt][q] = 0.f;

    float2 v0 = *(const float2*)(a0p),     v1 = *(const float2*)(a1p);
    float2 v2 = *(const float2*)(a0p + 8), v3 = *(const float2*)(a1p + 8);
    float2 w0 = *(const float2*)(a2p),     w1 = *(const float2*)(a3p);
    float2 w2 = *(const float2*)(a2p + 8), w3 = *(const float2*)(a3p + 8);

#pragma unroll 4
    for (int kk = 0; kk < 32; kk++) {
        uint32_t a0 = f2bf2(v0.x, v0.y), a1 = f2bf2(v1.x, v1.y);
        uint32_t a2 = f2bf2(v2.x, v2.y), a3 = f2bf2(v3.x, v3.y);
        uint32_t c0 = f2bf2(w0.x, w0.y), c1 = f2bf2(w1.x, w1.y);
        uint32_t c2 = f2bf2(w2.x, w2.y), c3 = f2bf2(w3.x, w3.y);
        if (kk < 31) {
            int k0 = (kk + 1) * 16;
            v0 = *(const float2*)(a0p + k0);     v1 = *(const float2*)(a1p + k0);
            v2 = *(const float2*)(a0p + k0 + 8); v3 = *(const float2*)(a1p + k0 + 8);
            w0 = *(const float2*)(a2p + k0);     w1 = *(const float2*)(a3p + k0);
            w2 = *(const float2*)(a2p + k0 + 8); w3 = *(const float2*)(a3p + k0 + 8);
        }
        const unsigned long long* rowp = sB + ((kk * 4 + tg) << 6) + (g ^ (tg << 1)) * 2;
#pragma unroll
        for (int p = 0; p < 4; p++) {
            uint4 bb = *(const uint4*)(rowp + p * 16);
            int n0 = 2 * p, n1 = 2 * p + 1;
            asm volatile(
                "mma.sync.aligned.m16n8k16.row.col.f32.bf16.bf16.f32 "
                "{%0,%1,%2,%3}, {%4,%5,%6,%7}, {%8,%9}, {%0,%1,%2,%3};"
                : "+f"(acc[n0][0]), "+f"(acc[n0][1]), "+f"(acc[n0][2]), "+f"(acc[n0][3])
                : "r"(a0), "r"(a1), "r"(a2), "r"(a3), "r"(bb.x), "r"(bb.y));
            asm volatile(
                "mma.sync.aligned.m16n8k16.row.col.f32.bf16.bf16.f32 "
                "{%0,%1,%2,%3}, {%4,%5,%6,%7}, {%8,%9}, {%0,%1,%2,%3};"
                : "+f"(acc[n1][0]), "+f"(acc[n1][1]), "+f"(acc[n1][2]), "+f"(acc[n1][3])
                : "r"(a0), "r"(a1), "r"(a2), "r"(a3), "r"(bb.z), "r"(bb.w));
            asm volatile(
                "mma.sync.aligned.m16n8k16.row.col.f32.bf16.bf16.f32 "
                "{%0,%1,%2,%3}, {%4,%5,%6,%7}, {%8,%9}, {%0,%1,%2,%3};"
                : "+f"(acc[n0 + 8][0]), "+f"(acc[n0 + 8][1]), "+f"(acc[n0 + 8][2]), "+f"(acc[n0 + 8][3])
                : "r"(c0), "r"(c1), "r"(c2), "r"(c3), "r"(bb.x), "r"(bb.y));
            asm volatile(
                "mma.sync.aligned.m16n8k16.row.col.f32.bf16.bf16.f32 "
                "{%0,%1,%2,%3}, {%4,%5,%6,%7}, {%8,%9}, {%0,%1,%2,%3};"
                : "+f"(acc[n1 + 8][0]), "+f"(acc[n1 + 8][1]), "+f"(acc[n1 + 8][2]), "+f"(acc[n1 + 8][3])
                : "r"(c0), "r"(c1), "r"(c2), "r"(c3), "r"(bb.z), "r"(bb.w));
        }
    }

    int r0 = row0 + g;
#pragma unroll
    for (int nt = 0; nt < 8; nt++) {
        int c = nt * 8 + tg * 2;
        float b0v = bias[c], b1v = bias[c + 1];
        float2 o;
        o.x = acc[nt][0] + b0v; o.y = acc[nt][1] + b1v;
        *(float2*)(g_em + (size_t)r0 * K_DIM + c) = o;
        o.x = acc[nt][2] + b0v; o.y = acc[nt][3] + b1v;
        *(float2*)(g_em + (size_t)(r0 + 8) * K_DIM + c) = o;
        o.x = acc[nt + 8][0] + b0v; o.y = acc[nt + 8][1] + b1v;
        *(float2*)(g_em + (size_t)(r0 + 16) * K_DIM + c) = o;
        o.x = acc[nt + 8][2] + b0v; o.y = acc[nt + 8][3] + b1v;
        *(float2*)(g_em + (size_t)(r0 + 24) * K_DIM + c) = o;
    }
}

// ---------------------------------------------------------------------------
// Kernel 2: CRF DP + gold + fused final reduction.
// 64-thread groups (named barriers), TWO batches per group sharing the eT
// registers. Branch-free step: normalize by v_0 (element 0 of the previous
// vector; x_0 = 1 so any positive scalar works) -> all threads compute
// rcp/log redundantly; exact because D compensates with log of the ACTUAL
// rcp value applied. Freeze-by-select for unequal lens.
// ---------------------------------------------------------------------------
#define FMA2(acc, a, b) \
    asm("fma.rn.f32x2 %0, %1, %2, %3;" : "=l"(acc) : "l"(a), "l"(b), "l"(acc))

__global__ __launch_bounds__(128) void crf_dp(const int* __restrict__ lens,
                                              const int* __restrict__ tags,
                                              const float* __restrict__ trans,
                                              const float* __restrict__ begin,
                                              const float* __restrict__ endt,
                                              float* __restrict__ out) {
    int tid  = threadIdx.x;
    int gid  = tid >> 6;          // group in block
    int j    = tid & 63;
    int lane = tid & 31;
    int wing = (tid >> 5) & 1;
    int base = blockIdx.x * 4 + gid * 2;   // batches: base, base+1
    int barid = gid + 1;

    int len0 = lens[base], len1 = lens[base + 1];
    int tmax = len0 > len1 ? len0 : len1;

    __shared__ __align__(16) float sm_u[2][2][2][64];  // [group][slot][buf][64]
    __shared__ float sm_g[2][2];

#define GBAR() asm volatile("bar.sync %0, 64;" :: "r"(barid) : "memory")

    // ---- gold path scores (both batches) ----
    float gold0 = 0.f, gold1 = 0.f;
#pragma unroll
    for (int m = 0; m < 2; m++) {
        int b = base + m, len = m ? len1 : len0;
        float gpart = 0.f;
        for (int t = j; t < len; t += 64) {
            int tag = tags[t * B_DIM + b];
            float inc;
            if (t == 0) inc = begin[tag];
            else        inc = trans[tag * K_DIM + tags[(t - 1) * B_DIM + b]];
            inc += g_em[((size_t)t * B_DIM + b) * K_DIM + tag];
            gpart += inc;
        }
#pragma unroll
        for (int o = 16; o; o >>= 1) gpart += __shfl_down_sync(0xffffffffu, gpart, o);
        if (lane == 0) sm_g[gid][wing] = gpart;
        GBAR();
        float gv = 0.f;
        if (j == 0)
            gv = sm_g[gid][0] + sm_g[gid][1] + endt[tags[(len - 1) * B_DIM + b]];
        GBAR();
        if (m) gold1 = gv; else gold0 = gv;
    }

    // ---- exp(transition) row j, packed f32x2 (shared by both batches) ----
    unsigned long long eT2[32];
    {
        const float4* tr4 = (const float4*)(trans + j * K_DIM);
#pragma unroll
        for (int q = 0; q < 16; q++) {
            float4 v = tr4[q];
            float e0 = __expf(v.x), e1 = __expf(v.y);
            float e2 = __expf(v.z), e3 = __expf(v.w);
            asm("mov.b64 %0, {%1,%2};" : "=l"(eT2[2*q])   : "f"(e0), "f"(e1));
            asm("mov.b64 %0, {%1,%2};" : "=l"(eT2[2*q+1]) : "f"(e2), "f"(e3));
        }
    }

    // ---- per-batch init + em pipelines ----
    float C0, C1, um0, um1;
    float xq0[2], e0q0[2], rawJ0[4], raw00[4];
    float xq1[2], e0q1[2], rawJ1[4], raw01[4];
#pragma unroll
    for (int m = 0; m < 2; m++) {
        int b = base + m, len = m ? len1 : len0;
        float a00 = begin[0] + g_em[(size_t)b * K_DIM];
        float u0  = __expf(begin[j] + g_em[(size_t)b * K_DIM + j] - a00);
        sm_u[gid][m][0][j] = u0;
        float* xq   = m ? xq1   : xq0;
        float* e0q  = m ? e0q1  : e0q0;
        float* rawJ = m ? rawJ1 : rawJ0;
        float* raw0 = m ? raw01 : raw00;
#pragma unroll
        for (int s = 0; s < 4; s++) {
            int idx = (3 + s < len) ? 3 + s : len - 1;
            size_t bb = ((size_t)idx * B_DIM + b) * K_DIM;
            rawJ[s] = g_em[bb + j];
            raw0[s] = g_em[bb];
        }
        int i1 = 1 < len ? 1 : len - 1;
        int i2 = 2 < len ? 2 : len - 1;
        size_t b1 = ((size_t)i1 * B_DIM + b) * K_DIM;
        size_t b2 = ((size_t)i2 * B_DIM + b) * K_DIM;
        float e1j = g_em[b1 + j], e10 = g_em[b1];
        float e2j = g_em[b2 + j], e20 = g_em[b2];
        xq[0] = __expf(e1j - e10); e0q[0] = e10;
        xq[1] = __expf(e2j - e20); e0q[1] = e20;
        if (m) { C1 = a00; um1 = u0; } else { C0 = a00; um0 = u0; }
    }

    // ---- serial DP: tmax-1 steps, ONE named barrier each, branch-free ----
#pragma unroll 4
    for (int t = 0; t < tmax - 1; t++) {
        int buf = t & 1, nbuf = buf ^ 1, p = t & 3;
        GBAR();

        const float* u0base = sm_u[gid][0][buf];
        const float* u1base = sm_u[gid][1][buf];

        // scalar broadcast loads of v_0 -> rcp issues under the dot
        float v00 = u0base[0];
        float v01 = u1base[0];
        float ir0, ir1;
        asm("rcp.approx.f32 %0, %1;" : "=f"(ir0) : "f"(v00));
        asm("rcp.approx.f32 %0, %1;" : "=f"(ir1) : "f"(v01));

        const ulonglong2* pp0 = (const ulonglong2*)u0base;
        const ulonglong2* pp1 = (const ulonglong2*)u1base;
        unsigned long long a0 = 0, a1 = 0, a2 = 0, a3 = 0;
        unsigned long long c0 = 0, c1 = 0, c2 = 0, c3 = 0;
#pragma unroll
        for (int q = 0; q < 16; q += 2) {
            ulonglong2 va0 = pp0[q],     vb0 = pp0[q + 1];
            ulonglong2 va1 = pp1[q],     vb1 = pp1[q + 1];
            FMA2(a0, va0.x, eT2[2*q]);   FMA2(a1, va0.y, eT2[2*q+1]);
            FMA2(a2, vb0.x, eT2[2*q+2]); FMA2(a3, vb0.y, eT2[2*q+3]);
            FMA2(c0, va1.x, eT2[2*q]);   FMA2(c1, va1.y, eT2[2*q+1]);
            FMA2(c2, vb1.x, eT2[2*q+2]); FMA2(c3, vb1.y, eT2[2*q+3]);
        }
        float s0, s1;
        {
            float p0, p1, p2, p3, p4, p5, p6, p7;
            asm("mov.b64 {%0,%1}, %2;" : "=f"(p0), "=f"(p1) : "l"(a0));
            asm("mov.b64 {%0,%1}, %2;" : "=f"(p2), "=f"(p3) : "l"(a1));
            asm("mov.b64 {%0,%1}, %2;" : "=f"(p4), "=f"(p5) : "l"(a2));
            asm("mov.b64 {%0,%1}, %2;" : "=f"(p6), "=f"(p7) : "l"(a3));
            s0 = ((p0 + p1) + (p2 + p3)) + ((p4 + p5) + (p6 + p7));
            asm("mov.b64 {%0,%1}, %2;" : "=f"(p0), "=f"(p1) : "l"(c0));
            asm("mov.b64 {%0,%1}, %2;" : "=f"(p2), "=f"(p3) : "l"(c1));
            asm("mov.b64 {%0,%1}, %2;" : "=f"(p4), "=f"(p5) : "l"(c2));
            asm("mov.b64 {%0,%1}, %2;" : "=f"(p6), "=f"(p7) : "l"(c3));
            s1 = ((p0 + p1) + (p2 + p3)) + ((p4 + p5) + (p6 + p7));
        }

        bool act0 = (t < len0 - 1), act1 = (t < len1 - 1);
        float un0 = s0 * (xq0[buf] * ir0);
        float un1 = s1 * (xq1[buf] * ir1);
        um0 = act0 ? un0 : um0;
        um1 = act1 ? un1 : um1;
        sm_u[gid][0][nbuf][j] = um0;
        sm_u[gid][1][nbuf][j] = um1;
        C0 += act0 ? (e0q0[buf] - __logf(ir0)) : 0.f;
        C1 += act1 ? (e0q1[buf] - __logf(ir1)) : 0.f;

        // refill exp stage (t+3) and raw ring (t+7) for both batches
        float r00 = raw00[p];
        xq0[buf] = __expf(rawJ0[p] - r00);
        e0q0[buf] = r00;
        int tl0 = (t + 7 < len0) ? t + 7 : len0 - 1;
        size_t base0 = ((size_t)tl0 * B_DIM + base) * K_DIM;
        rawJ0[p] = g_em[base0 + j];
        raw00[p] = g_em[base0];

        float r01 = raw01[p];
        xq1[buf] = __expf(rawJ1[p] - r01);
        e0q1[buf] = r01;
        int tl1 = (t + 7 < len1) ? t + 7 : len1 - 1;
        size_t base1 = ((size_t)tl1 * B_DIM + base + 1) * K_DIM;
        rawJ1[p] = g_em[base1 + j];
        raw01[p] = g_em[base1];
    }

    // ---- forward scores & output ----
#pragma unroll
    for (int m = 0; m < 2; m++) {
        float um = m ? um1 : um0;
        float C  = m ? C1  : C0;
        float gv = m ? gold1 : gold0;
        float val = um * __expf(endt[j]);
#pragma unroll
        for (int o = 16; o; o >>= 1) val += __shfl_down_sync(0xffffffffu, val, o);
        if (lane == 0) sm_g[gid][wing] = val;
        GBAR();
        if (j == 0) {
            float fwd = C + __logf(sm_g[gid][0] + sm_g[gid][1]);
            g_diff[base + m] = fwd - gv;
        }
        GBAR();
    }
#undef GBAR

    // ---- fused deterministic final reduction (last block) ----
    __syncthreads();
    __shared__ unsigned int s_last;
    if (tid == 0) {
        __threadfence();
        unsigned int old = atomicAdd(&g_cnt, 1u);
        s_last = (old == (unsigned)(gridDim.x - 1)) ? 1u : 0u;
    }
    __syncthreads();
    if (s_last) {
        __shared__ float sr[128];
        if (tid == 0) __threadfence();
        __syncthreads();
        float v = __ldcg(&g_diff[tid]) + __ldcg(&g_diff[tid + 128]);
        sr[tid] = v;
        __syncthreads();
        for (int k = 64; k > 0; k >>= 1) {
            if (tid < k) sr[tid] += sr[tid + k];
            __syncthreads();
        }
        if (tid == 0) {
            out[0] = sr[0];
            g_cnt = 0;   // reset for next graph replay
        }
    }
}

// ---------------------------------------------------------------------------
extern "C" void kernel_launch(void* const* d_in, const int* in_sizes, int n_in,
                              void* d_out, int out_size) {
    const float* hiddens = (const float*)d_in[0];   // [T,B,H] f32
    const int*   lens    = (const int*)d_in[1];     // [B]
    const int*   tags    = (const int*)d_in[2];     // [T,B]
    const float* W       = (const float*)d_in[3];   // [K,H]
    const float* bias    = (const float*)d_in[4];   // [K]
    const float* begin   = (const float*)d_in[5];   // [K]
    const float* trans   = (const float*)d_in[6];   // [K,K]
    const float* endt    = (const float*)d_in[7];   // [K]
    float* out = (float*)d_out;

    cudaFuncSetAttribute(emis_gemm, cudaFuncAttributeMaxDynamicSharedMemorySize, 65536);

    emis_gemm<<<M_DIM / 256, 256, 65536>>>(hiddens, W, bias);
    crf_dp<<<B_DIM / 4, 128>>>(lens, tags, trans, begin, endt, out);
}

// round 9
// speedup vs baseline: 1.4549x; 1.4549x over previous
#include <cuda_runtime.h>
#include <cuda_bf16.h>
#include <cstdint>

#define T_DIM 256
#define B_DIM 256
#define H_DIM 512
#define K_DIM 64
#define M_DIM (T_DIM * B_DIM)

// Scratch (device globals; no allocations anywhere)
__device__ float g_em[(size_t)M_DIM * K_DIM];   // emissions [T,B,K] f32
__device__ float g_diff[B_DIM];                 // per-batch forward - gold
__device__ unsigned int g_cnt = 0;              // last-block counter (self-resetting)

__device__ __forceinline__ uint32_t f2bf2(float lo, float hi) {
    uint32_t r;
    asm("cvt.rn.bf16x2.f32 %0, %1, %2;" : "=r"(r) : "f"(hi), "f"(lo));
    return r;
}

// ---------------------------------------------------------------------------
// Kernel 1: emissions GEMM  (unchanged; 54.0us measured)
// ---------------------------------------------------------------------------
extern __shared__ unsigned long long sB[];   // 8192 u64 = 64 KB dynamic

__global__ __launch_bounds__(256, 2) void emis_gemm(const float* __restrict__ hid,
                                                    const float* __restrict__ W,
                                                    const float* __restrict__ bias) {
    int tid = threadIdx.x;

    for (int i = tid; i < (K_DIM * H_DIM) / 4; i += 256) {
        int n  = i >> 7;
        int r  = i & 127;
        int kk = r >> 2;
        int tg = r & 3;
        const float2* src = (const float2*)(W + n * H_DIM + kk * 16 + tg * 2);
        float2 lo = src[0];
        float2 hi = src[4];
        uint32_t wl = f2bf2(lo.x, lo.y);
        uint32_t wh = f2bf2(hi.x, hi.y);
        unsigned long long u;
        asm("mov.b64 %0, {%1,%2};" : "=l"(u) : "r"(wl), "r"(wh));
        int g = n & 7, nt = n >> 3;
        int p = nt >> 1, half = nt & 1;
        sB[(kk * 4 + tg) * 64 + (p * 8 + (g ^ (tg << 1))) * 2 + half] = u;
    }
    __syncthreads();

    int warp = tid >> 5;
    int lane = tid & 31;
    int g  = lane >> 2;
    int tg = lane & 3;
    int row0 = blockIdx.x * 256 + warp * 32;

    const float* a0p = hid + (size_t)(row0 + g)      * H_DIM + tg * 2;
    const float* a1p = hid + (size_t)(row0 + g + 8)  * H_DIM + tg * 2;
    const float* a2p = hid + (size_t)(row0 + g + 16) * H_DIM + tg * 2;
    const float* a3p = hid + (size_t)(row0 + g + 24) * H_DIM + tg * 2;

    float acc[16][4];
#pragma unroll
    for (int nt = 0; nt < 16; nt++)
#pragma unroll
        for (int q = 0; q < 4; q++) acc[nt][q] = 0.f;

    float2 v0 = *(const float2*)(a0p),     v1 = *(const float2*)(a1p);
    float2 v2 = *(const float2*)(a0p + 8), v3 = *(const float2*)(a1p + 8);
    float2 w0 = *(const float2*)(a2p),     w1 = *(const float2*)(a3p);
    float2 w2 = *(const float2*)(a2p + 8), w3 = *(const float2*)(a3p + 8);

#pragma unroll 4
    for (int kk = 0; kk < 32; kk++) {
        uint32_t a0 = f2bf2(v0.x, v0.y), a1 = f2bf2(v1.x, v1.y);
        uint32_t a2 = f2bf2(v2.x, v2.y), a3 = f2bf2(v3.x, v3.y);
        uint32_t c0 = f2bf2(w0.x, w0.y), c1 = f2bf2(w1.x, w1.y);
        uint32_t c2 = f2bf2(w2.x, w2.y), c3 = f2bf2(w3.x, w3.y);
        if (kk < 31) {
            int k0 = (kk + 1) * 16;
            v0 = *(const float2*)(a0p + k0);     v1 = *(const float2*)(a1p + k0);
            v2 = *(const float2*)(a0p + k0 + 8); v3 = *(const float2*)(a1p + k0 + 8);
            w0 = *(const float2*)(a2p + k0);     w1 = *(const float2*)(a3p + k0);
            w2 = *(const float2*)(a2p + k0 + 8); w3 = *(const float2*)(a3p + k0 + 8);
        }
        const unsigned long long* rowp = sB + ((kk * 4 + tg) << 6) + (g ^ (tg << 1)) * 2;
#pragma unroll
        for (int p = 0; p < 4; p++) {
            uint4 bb = *(const uint4*)(rowp + p * 16);
            int n0 = 2 * p, n1 = 2 * p + 1;
            asm volatile(
                "mma.sync.aligned.m16n8k16.row.col.f32.bf16.bf16.f32 "
                "{%0,%1,%2,%3}, {%4,%5,%6,%7}, {%8,%9}, {%0,%1,%2,%3};"
                : "+f"(acc[n0][0]), "+f"(acc[n0][1]), "+f"(acc[n0][2]), "+f"(acc[n0][3])
                : "r"(a0), "r"(a1), "r"(a2), "r"(a3), "r"(bb.x), "r"(bb.y));
            asm volatile(
                "mma.sync.aligned.m16n8k16.row.col.f32.bf16.bf16.f32 "
                "{%0,%1,%2,%3}, {%4,%5,%6,%7}, {%8,%9}, {%0,%1,%2,%3};"
                : "+f"(acc[n1][0]), "+f"(acc[n1][1]), "+f"(acc[n1][2]), "+f"(acc[n1][3])
                : "r"(a0), "r"(a1), "r"(a2), "r"(a3), "r"(bb.z), "r"(bb.w));
            asm volatile(
                "mma.sync.aligned.m16n8k16.row.col.f32.bf16.bf16.f32 "
                "{%0,%1,%2,%3}, {%4,%5,%6,%7}, {%8,%9}, {%0,%1,%2,%3};"
                : "+f"(acc[n0 + 8][0]), "+f"(acc[n0 + 8][1]), "+f"(acc[n0 + 8][2]), "+f"(acc[n0 + 8][3])
                : "r"(c0), "r"(c1), "r"(c2), "r"(c3), "r"(bb.x), "r"(bb.y));
            asm volatile(
                "mma.sync.aligned.m16n8k16.row.col.f32.bf16.bf16.f32 "
                "{%0,%1,%2,%3}, {%4,%5,%6,%7}, {%8,%9}, {%0,%1,%2,%3};"
                : "+f"(acc[n1 + 8][0]), "+f"(acc[n1 + 8][1]), "+f"(acc[n1 + 8][2]), "+f"(acc[n1 + 8][3])
                : "r"(c0), "r"(c1), "r"(c2), "r"(c3), "r"(bb.z), "r"(bb.w));
        }
    }

    int r0 = row0 + g;
#pragma unroll
    for (int nt = 0; nt < 8; nt++) {
        int c = nt * 8 + tg * 2;
        float b0v = bias[c], b1v = bias[c + 1];
        float2 o;
        o.x = acc[nt][0] + b0v; o.y = acc[nt][1] + b1v;
        *(float2*)(g_em + (size_t)r0 * K_DIM + c) = o;
        o.x = acc[nt][2] + b0v; o.y = acc[nt][3] + b1v;
        *(float2*)(g_em + (size_t)(r0 + 8) * K_DIM + c) = o;
        o.x = acc[nt + 8][0] + b0v; o.y = acc[nt + 8][1] + b1v;
        *(float2*)(g_em + (size_t)(r0 + 16) * K_DIM + c) = o;
        o.x = acc[nt + 8][2] + b0v; o.y = acc[nt + 8][3] + b1v;
        *(float2*)(g_em + (size_t)(r0 + 24) * K_DIM + c) = o;
    }
}

// ---------------------------------------------------------------------------
// Kernel 2: CRF DP + gold + fused final reduction.
// R6 structure (grid 128, 2 independent 64-thread groups per block, ONE batch
// per group, one named barrier per step) + branch-free v0-normalization:
// ir = rcp(u_prev[0]) computed by ALL threads (broadcast LDS + MUFU hidden
// under the dot); C += em0 - log(ir) accumulated redundantly -> no j==0
// divergent tail, no sm_inv round-trip. Exact: C compensates the ACTUAL ir.
// ---------------------------------------------------------------------------
#define FMA2(acc, a, b) \
    asm("fma.rn.f32x2 %0, %1, %2, %3;" : "=l"(acc) : "l"(a), "l"(b), "l"(acc))

__global__ __launch_bounds__(128) void crf_dp(const int* __restrict__ lens,
                                              const int* __restrict__ tags,
                                              const float* __restrict__ trans,
                                              const float* __restrict__ begin,
                                              const float* __restrict__ endt,
                                              float* __restrict__ out) {
    int tid  = threadIdx.x;
    int gid  = tid >> 6;
    int j    = tid & 63;
    int lane = tid & 31;
    int wing = (tid >> 5) & 1;
    int b    = blockIdx.x * 2 + gid;
    int len  = lens[b];
    int barid = gid + 1;

    __shared__ __align__(16) float sm_u[2][2][64];
    __shared__ float sm_g[2][2];

#define GBAR() asm volatile("bar.sync %0, 64;" :: "r"(barid) : "memory")

    // ---- gold path score ----
    float gpart = 0.f;
    for (int t = j; t < len; t += 64) {
        int tag = tags[t * B_DIM + b];
        float inc;
        if (t == 0) inc = begin[tag];
        else        inc = trans[tag * K_DIM + tags[(t - 1) * B_DIM + b]];
        inc += g_em[((size_t)t * B_DIM + b) * K_DIM + tag];
        gpart += inc;
    }
#pragma unroll
    for (int o = 16; o; o >>= 1) gpart += __shfl_down_sync(0xffffffffu, gpart, o);
    if (lane == 0) sm_g[gid][wing] = gpart;
    GBAR();
    float goldv = 0.f;
    if (j == 0)
        goldv = sm_g[gid][0] + sm_g[gid][1] + endt[tags[(len - 1) * B_DIM + b]];

    // ---- exp(transition) row j, packed f32x2 ----
    unsigned long long eT2[32];
    {
        const float4* tr4 = (const float4*)(trans + j * K_DIM);
#pragma unroll
        for (int q = 0; q < 16; q++) {
            float4 v = tr4[q];
            float e0 = __expf(v.x), e1 = __expf(v.y);
            float e2 = __expf(v.z), e3 = __expf(v.w);
            asm("mov.b64 %0, {%1,%2};" : "=l"(eT2[2*q])   : "f"(e0), "f"(e1));
            asm("mov.b64 %0, {%1,%2};" : "=l"(eT2[2*q+1]) : "f"(e2), "f"(e3));
        }
    }

    // ---- init (t=0): u0_j = exp(alpha_j(0) - alpha_0(0)); Z(0) = alpha_0(0) ----
    float a00 = begin[0] + g_em[(size_t)b * K_DIM];
    float u0  = __expf(begin[j] + g_em[(size_t)b * K_DIM + j] - a00);
    float C = a00;                      // accumulated redundantly by all threads
    sm_u[gid][0][j] = u0;
    float u_reg = u0;

    // ---- em pipeline (depth-4 raw ring + depth-2 exp stage, as R6) ----
    float xq[2], e0q[2];
    float rawJ[4], raw0[4];
    {
#pragma unroll
        for (int s = 0; s < 4; s++) {
            int idx = (3 + s < len) ? 3 + s : len - 1;
            size_t base = ((size_t)idx * B_DIM + b) * K_DIM;
            rawJ[s] = g_em[base + j];
            raw0[s] = g_em[base];
        }
        int i1 = 1 < len ? 1 : len - 1;
        int i2 = 2 < len ? 2 : len - 1;
        size_t b1 = ((size_t)i1 * B_DIM + b) * K_DIM;
        size_t b2 = ((size_t)i2 * B_DIM + b) * K_DIM;
        float e1j = g_em[b1 + j], e10 = g_em[b1];
        float e2j = g_em[b2 + j], e20 = g_em[b2];
        xq[0] = __expf(e1j - e10); e0q[0] = e10;
        xq[1] = __expf(e2j - e20); e0q[1] = e20;
    }

    // ---- serial DP: len-1 steps, ONE named barrier each, branch-free ----
#pragma unroll 4
    for (int t = 0; t < len - 1; t++) {
        int buf = t & 1, nbuf = buf ^ 1, p = t & 3;
        GBAR();

        const float* ubase = sm_u[gid][buf];
        // broadcast scalar load of u_prev[0]; rcp hides under the dot
        float v0 = ubase[0];
        float ir;
        asm("rcp.approx.f32 %0, %1;" : "=f"(ir) : "f"(v0));

        const ulonglong2* pp = (const ulonglong2*)ubase;
        unsigned long long acc0 = 0, acc1 = 0, acc2 = 0, acc3 = 0;
#pragma unroll
        for (int q = 0; q < 16; q += 2) {
            ulonglong2 va = pp[q];
            ulonglong2 vb = pp[q + 1];
            FMA2(acc0, va.x, eT2[2*q]);
            FMA2(acc1, va.y, eT2[2*q+1]);
            FMA2(acc2, vb.x, eT2[2*q+2]);
            FMA2(acc3, vb.y, eT2[2*q+3]);
        }
        float s;
        {
            float l0, h0, l1, h1, l2, h2, l3, h3;
            asm("mov.b64 {%0,%1}, %2;" : "=f"(l0), "=f"(h0) : "l"(acc0));
            asm("mov.b64 {%0,%1}, %2;" : "=f"(l1), "=f"(h1) : "l"(acc1));
            asm("mov.b64 {%0,%1}, %2;" : "=f"(l2), "=f"(h2) : "l"(acc2));
            asm("mov.b64 {%0,%1}, %2;" : "=f"(l3), "=f"(h3) : "l"(acc3));
            s = ((l0 + h0) + (l1 + h1)) + ((l2 + h2) + (l3 + h3));
        }
        float un = s * (xq[buf] * ir);
        sm_u[gid][nbuf][j] = un;
        u_reg = un;
        C += e0q[buf] - __logf(ir);      // off u-critical path; exact compensation

        // refill exp stage (t+3) and raw ring (t+7)
        float r0 = raw0[p];
        xq[buf] = __expf(rawJ[p] - r0);
        e0q[buf] = r0;
        int tl = (t + 7 < len) ? t + 7 : len - 1;
        size_t base = ((size_t)tl * B_DIM + b) * K_DIM;
        rawJ[p] = g_em[base + j];
        raw0[p] = g_em[base];
    }

    // ---- forward = C + log(sum_j u_j * exp(end_j)) ----
    float val = u_reg * __expf(endt[j]);
#pragma unroll
    for (int o = 16; o; o >>= 1) val += __shfl_down_sync(0xffffffffu, val, o);
    if (lane == 0) sm_g[gid][wing] = val;
    GBAR();
    if (j == 0) {
        float fwd = C + __logf(sm_g[gid][0] + sm_g[gid][1]);
        g_diff[b] = fwd - goldv;
    }
#undef GBAR

    // ---- fused deterministic final reduction (last block) ----
    __syncthreads();
    __shared__ unsigned int s_last;
    if (tid == 0) {
        __threadfence();
        unsigned int old = atomicAdd(&g_cnt, 1u);
        s_last = (old == (unsigned)(gridDim.x - 1)) ? 1u : 0u;
    }
    __syncthreads();
    if (s_last) {
        __shared__ float sr[128];
        if (tid == 0) __threadfence();
        __syncthreads();
        float v = __ldcg(&g_diff[tid]) + __ldcg(&g_diff[tid + 128]);
        sr[tid] = v;
        __syncthreads();
        for (int k = 64; k > 0; k >>= 1) {
            if (tid < k) sr[tid] += sr[tid + k];
            __syncthreads();
        }
        if (tid == 0) {
            out[0] = sr[0];
            g_cnt = 0;   // reset for next graph replay
        }
    }
}

// ---------------------------------------------------------------------------
extern "C" void kernel_launch(void* const* d_in, const int* in_sizes, int n_in,
                              void* d_out, int out_size) {
    const float* hiddens = (const float*)d_in[0];   // [T,B,H] f32
    const int*   lens    = (const int*)d_in[1];     // [B]
    const int*   tags    = (const int*)d_in[2];     // [T,B]
    const float* W       = (const float*)d_in[3];   // [K,H]
    const float* bias    = (const float*)d_in[4];   // [K]
    const float* begin   = (const float*)d_in[5];   // [K]
    const float* trans   = (const float*)d_in[6];   // [K,K]
    const float* endt    = (const float*)d_in[7];   // [K]
    float* out = (float*)d_out;

    cudaFuncSetAttribute(emis_gemm, cudaFuncAttributeMaxDynamicSharedMemorySize, 65536);

    emis_gemm<<<M_DIM / 256, 256, 65536>>>(hiddens, W, bias);
    crf_dp<<<B_DIM / 2, 128>>>(lens, tags, trans, begin, endt, out);
}

// round 10
// speedup vs baseline: 1.8917x; 1.3002x over previous
#include <cuda_runtime.h>
#include <cuda_bf16.h>
#include <cstdint>

#define T_DIM 256
#define B_DIM 256
#define H_DIM 512
#define K_DIM 64
#define M_DIM (T_DIM * B_DIM)

// Scratch (device globals; no allocations anywhere)
__device__ float g_em[(size_t)M_DIM * K_DIM];   // emissions [T,B,K] f32
__device__ float g_diff[B_DIM];                 // per-batch forward - gold
__device__ unsigned int g_cnt = 0;              // last-block counter (self-resetting)

__device__ __forceinline__ uint32_t f2bf2(float lo, float hi) {
    uint32_t r;
    asm("cvt.rn.bf16x2.f32 %0, %1, %2;" : "=r"(r) : "f"(hi), "f"(lo));
    return r;
}

// ---------------------------------------------------------------------------
// Kernel 1: emissions GEMM  (unchanged; ~54us)
// ---------------------------------------------------------------------------
extern __shared__ unsigned long long sB[];   // 8192 u64 = 64 KB dynamic

__global__ __launch_bounds__(256, 2) void emis_gemm(const float* __restrict__ hid,
                                                    const float* __restrict__ W,
                                                    const float* __restrict__ bias) {
    int tid = threadIdx.x;

    for (int i = tid; i < (K_DIM * H_DIM) / 4; i += 256) {
        int n  = i >> 7;
        int r  = i & 127;
        int kk = r >> 2;
        int tg = r & 3;
        const float2* src = (const float2*)(W + n * H_DIM + kk * 16 + tg * 2);
        float2 lo = src[0];
        float2 hi = src[4];
        uint32_t wl = f2bf2(lo.x, lo.y);
        uint32_t wh = f2bf2(hi.x, hi.y);
        unsigned long long u;
        asm("mov.b64 %0, {%1,%2};" : "=l"(u) : "r"(wl), "r"(wh));
        int g = n & 7, nt = n >> 3;
        int p = nt >> 1, half = nt & 1;
        sB[(kk * 4 + tg) * 64 + (p * 8 + (g ^ (tg << 1))) * 2 + half] = u;
    }
    __syncthreads();

    int warp = tid >> 5;
    int lane = tid & 31;
    int g  = lane >> 2;
    int tg = lane & 3;
    int row0 = blockIdx.x * 256 + warp * 32;

    const float* a0p = hid + (size_t)(row0 + g)      * H_DIM + tg * 2;
    const float* a1p = hid + (size_t)(row0 + g + 8)  * H_DIM + tg * 2;
    const float* a2p = hid + (size_t)(row0 + g + 16) * H_DIM + tg * 2;
    const float* a3p = hid + (size_t)(row0 + g + 24) * H_DIM + tg * 2;

    float acc[16][4];
#pragma unroll
    for (int nt = 0; nt < 16; nt++)
#pragma unroll
        for (int q = 0; q < 4; q++) acc[nt][q] = 0.f;

    float2 v0 = *(const float2*)(a0p),     v1 = *(const float2*)(a1p);
    float2 v2 = *(const float2*)(a0p + 8), v3 = *(const float2*)(a1p + 8);
    float2 w0 = *(const float2*)(a2p),     w1 = *(const float2*)(a3p);
    float2 w2 = *(const float2*)(a2p + 8), w3 = *(const float2*)(a3p + 8);

#pragma unroll 4
    for (int kk = 0; kk < 32; kk++) {
        uint32_t a0 = f2bf2(v0.x, v0.y), a1 = f2bf2(v1.x, v1.y);
        uint32_t a2 = f2bf2(v2.x, v2.y), a3 = f2bf2(v3.x, v3.y);
        uint32_t c0 = f2bf2(w0.x, w0.y), c1 = f2bf2(w1.x, w1.y);
        uint32_t c2 = f2bf2(w2.x, w2.y), c3 = f2bf2(w3.x, w3.y);
        if (kk < 31) {
            int k0 = (kk + 1) * 16;
            v0 = *(const float2*)(a0p + k0);     v1 = *(const float2*)(a1p + k0);
            v2 = *(const float2*)(a0p + k0 + 8); v3 = *(const float2*)(a1p + k0 + 8);
            w0 = *(const float2*)(a2p + k0);     w1 = *(const float2*)(a3p + k0);
            w2 = *(const float2*)(a2p + k0 + 8); w3 = *(const float2*)(a3p + k0 + 8);
        }
        const unsigned long long* rowp = sB + ((kk * 4 + tg) << 6) + (g ^ (tg << 1)) * 2;
#pragma unroll
        for (int p = 0; p < 4; p++) {
            uint4 bb = *(const uint4*)(rowp + p * 16);
            int n0 = 2 * p, n1 = 2 * p + 1;
            asm volatile(
                "mma.sync.aligned.m16n8k16.row.col.f32.bf16.bf16.f32 "
                "{%0,%1,%2,%3}, {%4,%5,%6,%7}, {%8,%9}, {%0,%1,%2,%3};"
                : "+f"(acc[n0][0]), "+f"(acc[n0][1]), "+f"(acc[n0][2]), "+f"(acc[n0][3])
                : "r"(a0), "r"(a1), "r"(a2), "r"(a3), "r"(bb.x), "r"(bb.y));
            asm volatile(
                "mma.sync.aligned.m16n8k16.row.col.f32.bf16.bf16.f32 "
                "{%0,%1,%2,%3}, {%4,%5,%6,%7}, {%8,%9}, {%0,%1,%2,%3};"
                : "+f"(acc[n1][0]), "+f"(acc[n1][1]), "+f"(acc[n1][2]), "+f"(acc[n1][3])
                : "r"(a0), "r"(a1), "r"(a2), "r"(a3), "r"(bb.z), "r"(bb.w));
            asm volatile(
                "mma.sync.aligned.m16n8k16.row.col.f32.bf16.bf16.f32 "
                "{%0,%1,%2,%3}, {%4,%5,%6,%7}, {%8,%9}, {%0,%1,%2,%3};"
                : "+f"(acc[n0 + 8][0]), "+f"(acc[n0 + 8][1]), "+f"(acc[n0 + 8][2]), "+f"(acc[n0 + 8][3])
                : "r"(c0), "r"(c1), "r"(c2), "r"(c3), "r"(bb.x), "r"(bb.y));
            asm volatile(
                "mma.sync.aligned.m16n8k16.row.col.f32.bf16.bf16.f32 "
                "{%0,%1,%2,%3}, {%4,%5,%6,%7}, {%8,%9}, {%0,%1,%2,%3};"
                : "+f"(acc[n1 + 8][0]), "+f"(acc[n1 + 8][1]), "+f"(acc[n1 + 8][2]), "+f"(acc[n1 + 8][3])
                : "r"(c0), "r"(c1), "r"(c2), "r"(c3), "r"(bb.z), "r"(bb.w));
        }
    }

    int r0 = row0 + g;
#pragma unroll
    for (int nt = 0; nt < 8; nt++) {
        int c = nt * 8 + tg * 2;
        float b0v = bias[c], b1v = bias[c + 1];
        float2 o;
        o.x = acc[nt][0] + b0v; o.y = acc[nt][1] + b1v;
        *(float2*)(g_em + (size_t)r0 * K_DIM + c) = o;
        o.x = acc[nt][2] + b0v; o.y = acc[nt][3] + b1v;
        *(float2*)(g_em + (size_t)(r0 + 8) * K_DIM + c) = o;
        o.x = acc[nt + 8][0] + b0v; o.y = acc[nt + 8][1] + b1v;
        *(float2*)(g_em + (size_t)(r0 + 16) * K_DIM + c) = o;
        o.x = acc[nt + 8][2] + b0v; o.y = acc[nt + 8][3] + b1v;
        *(float2*)(g_em + (size_t)(r0 + 24) * K_DIM + c) = o;
    }
}

// ---------------------------------------------------------------------------
// Kernel 2: BIDIRECTIONAL CRF DP + gold + fused final reduction.
// 256 thr = 4 groups of 64; block handles 2 batches; per batch one FORWARD
// group (alpha: t=0..mid) and one BACKWARD group (beta: t=len-1..mid) run
// concurrently -> serial chain halves. Same per-step body as R6/R9:
// named barrier + smem double-buffer + v0-normalized linear recurrence.
//   fwd: u' = (E u) * x(t+1) * ir            C += em0(t+1) - log(ir)
//   bwd: store P = x(s) .* w;  w' = (E^T P) * ir;  C += em0(s) - log(ir)
// combine: score = Cf + Cb + log sum_j u_j(mid) * w_j(mid).
// ---------------------------------------------------------------------------
#define FMA2(acc, a, b) \
    asm("fma.rn.f32x2 %0, %1, %2, %3;" : "=l"(acc) : "l"(a), "l"(b), "l"(acc))

__global__ __launch_bounds__(256) void crf_dp(const int* __restrict__ lens,
                                              const int* __restrict__ tags,
                                              const float* __restrict__ trans,
                                              const float* __restrict__ begin,
                                              const float* __restrict__ endt,
                                              float* __restrict__ out) {
    int tid  = threadIdx.x;
    int gid  = tid >> 6;          // 0..3
    int j    = tid & 63;
    int lane = tid & 31;
    int wing = (tid >> 5) & 1;
    int pair = gid >> 1;          // 0,1: batch within block
    int bw   = gid & 1;           // 0 = forward, 1 = backward
    int b    = blockIdx.x * 2 + pair;
    int len  = lens[b];
    int barid   = gid + 1;        // group barrier (64 thr)
    int pairbar = 5 + pair;       // pair barrier (128 thr)

    int mid    = (len - 1) >> 1;
    int nsteps = bw ? (len - 1 - mid) : mid;

    __shared__ __align__(16) float sm_u[4][2][64];
    __shared__ __align__(16) float sm_fin[2][64];
    __shared__ float sm_g[4][2];
    __shared__ float sm_cb[2];

#define GBAR()  asm volatile("bar.sync %0, 64;"  :: "r"(barid)   : "memory")
#define PBAR()  asm volatile("bar.sync %0, 128;" :: "r"(pairbar) : "memory")

    // ---- gold path score (forward groups only; own group barrier) ----
    float goldv = 0.f;
    if (!bw) {
        float gpart = 0.f;
        for (int t = j; t < len; t += 64) {
            int tag = tags[t * B_DIM + b];
            float inc;
            if (t == 0) inc = begin[tag];
            else        inc = trans[tag * K_DIM + tags[(t - 1) * B_DIM + b]];
            inc += g_em[((size_t)t * B_DIM + b) * K_DIM + tag];
            gpart += inc;
        }
#pragma unroll
        for (int o = 16; o; o >>= 1) gpart += __shfl_down_sync(0xffffffffu, gpart, o);
        if (lane == 0) sm_g[gid][wing] = gpart;
        GBAR();
        if (j == 0)
            goldv = sm_g[gid][0] + sm_g[gid][1] + endt[tags[(len - 1) * B_DIM + b]];
    }

    // ---- exp(transition): fwd = row j of E, bwd = column j (row of E^T) ----
    unsigned long long eT2[32];
    if (!bw) {
        const float4* tr4 = (const float4*)(trans + j * K_DIM);
#pragma unroll
        for (int q = 0; q < 16; q++) {
            float4 v = tr4[q];
            float e0 = __expf(v.x), e1 = __expf(v.y);
            float e2 = __expf(v.z), e3 = __expf(v.w);
            asm("mov.b64 %0, {%1,%2};" : "=l"(eT2[2*q])   : "f"(e0), "f"(e1));
            asm("mov.b64 %0, {%1,%2};" : "=l"(eT2[2*q+1]) : "f"(e2), "f"(e3));
        }
    } else {
#pragma unroll
        for (int q = 0; q < 32; q++) {
            float t0 = __expf(trans[(2 * q) * K_DIM + j]);       // coalesced over j
            float t1 = __expf(trans[(2 * q + 1) * K_DIM + j]);
            asm("mov.b64 %0, {%1,%2};" : "=l"(eT2[q]) : "f"(t0), "f"(t1));
        }
    }

    // ---- consume-time map: fwd step k uses em[k+1]; bwd step k uses em[len-1-k]
#define CT(k) ({ int _v = bw ? (len - 1 - (k)) : ((k) + 1); \
                 _v = _v < 0 ? 0 : (_v > len - 1 ? len - 1 : _v); _v; })

    // ---- init ----
    float u_reg, C;
    if (!bw) {
        float a00 = begin[0] + g_em[(size_t)b * K_DIM];
        u_reg = __expf(begin[j] + g_em[(size_t)b * K_DIM + j] - a00);
        C = a00;
    } else {
        float e0 = endt[0];
        u_reg = __expf(endt[j] - e0);
        C = e0;
    }

    // em pipeline: xq = exp stage (depth 2), raw = LDG ring (depth 4)
    float xq[2], e0q[2];
    float rawJ[4], raw0[4];
    {
#pragma unroll
        for (int s = 0; s < 4; s++) {
            size_t base = ((size_t)CT(s + 2) * B_DIM + b) * K_DIM;
            rawJ[s] = g_em[base + j];
            raw0[s] = g_em[base];
        }
        size_t b1 = ((size_t)CT(0) * B_DIM + b) * K_DIM;
        size_t b2 = ((size_t)CT(1) * B_DIM + b) * K_DIM;
        float e1j = g_em[b1 + j], e10 = g_em[b1];
        float e2j = g_em[b2 + j], e20 = g_em[b2];
        xq[0] = __expf(e1j - e10); e0q[0] = e10;
        xq[1] = __expf(e2j - e20); e0q[1] = e20;
    }
    // initial stored vector: fwd = u ; bwd = x(len-1) .* w
    sm_u[gid][0][j] = bw ? (u_reg * xq[0]) : u_reg;

    // ---- serial DP: nsteps, ONE named barrier each ----
#pragma unroll 4
    for (int k = 0; k < nsteps; k++) {
        int buf = k & 1, nbuf = buf ^ 1, p = k & 3;
        GBAR();

        const float* ubase = sm_u[gid][buf];
        float v0 = ubase[0];
        float ir;
        asm("rcp.approx.f32 %0, %1;" : "=f"(ir) : "f"(v0));

        const ulonglong2* pp = (const ulonglong2*)ubase;
        unsigned long long acc0 = 0, acc1 = 0, acc2 = 0, acc3 = 0;
#pragma unroll
        for (int q = 0; q < 16; q += 2) {
            ulonglong2 va = pp[q];
            ulonglong2 vb = pp[q + 1];
            FMA2(acc0, va.x, eT2[2*q]);
            FMA2(acc1, va.y, eT2[2*q+1]);
            FMA2(acc2, vb.x, eT2[2*q+2]);
            FMA2(acc3, vb.y, eT2[2*q+3]);
        }
        float s;
        {
            float l0, h0, l1, h1, l2, h2, l3, h3;
            asm("mov.b64 {%0,%1}, %2;" : "=f"(l0), "=f"(h0) : "l"(acc0));
            asm("mov.b64 {%0,%1}, %2;" : "=f"(l1), "=f"(h1) : "l"(acc1));
            asm("mov.b64 {%0,%1}, %2;" : "=f"(l2), "=f"(h2) : "l"(acc2));
            asm("mov.b64 {%0,%1}, %2;" : "=f"(l3), "=f"(h3) : "l"(acc3));
            s = ((l0 + h0) + (l1 + h1)) + ((l2 + h2) + (l3 + h3));
        }
        float un = bw ? (s * ir) : (s * (xq[buf] * ir));
        u_reg = un;
        C += e0q[buf] - __logf(ir);
        // store for next step: bwd pre-multiplies by x of the NEXT consumed time
        sm_u[gid][nbuf][j] = bw ? (un * xq[nbuf]) : un;

        // refill exp stage (consume time k+2) and raw ring (consume time k+6)
        float r0 = raw0[p];
        xq[buf] = __expf(rawJ[p] - r0);
        e0q[buf] = r0;
        size_t base = ((size_t)CT(k + 6) * B_DIM + b) * K_DIM;
        rawJ[p] = g_em[base + j];
        raw0[p] = g_em[base];
    }
#undef CT

    // ---- meet in the middle ----
    if (bw) {
        sm_fin[pair][j] = u_reg;
        if (j == 0) sm_cb[pair] = C;
    }
    PBAR();
    if (!bw) {
        float val = u_reg * sm_fin[pair][j];
#pragma unroll
        for (int o = 16; o; o >>= 1) val += __shfl_down_sync(0xffffffffu, val, o);
        if (lane == 0) sm_g[gid][wing] = val;
        GBAR();
        if (j == 0) {
            float fwd = C + sm_cb[pair] + __logf(sm_g[gid][0] + sm_g[gid][1]);
            g_diff[b] = fwd - goldv;
        }
    }
#undef GBAR
#undef PBAR

    // ---- fused deterministic final reduction (last block) ----
    __syncthreads();
    __shared__ unsigned int s_last;
    if (tid == 0) {
        __threadfence();
        unsigned int old = atomicAdd(&g_cnt, 1u);
        s_last = (old == (unsigned)(gridDim.x - 1)) ? 1u : 0u;
    }
    __syncthreads();
    if (s_last) {
        __shared__ float sr[256];
        if (tid == 0) __threadfence();
        __syncthreads();
        sr[tid] = __ldcg(&g_diff[tid]);
        __syncthreads();
        for (int k = 128; k > 0; k >>= 1) {
            if (tid < k) sr[tid] += sr[tid + k];
            __syncthreads();
        }
        if (tid == 0) {
            out[0] = sr[0];
            g_cnt = 0;   // reset for next graph replay
        }
    }
}

// ---------------------------------------------------------------------------
extern "C" void kernel_launch(void* const* d_in, const int* in_sizes, int n_in,
                              void* d_out, int out_size) {
    const float* hiddens = (const float*)d_in[0];   // [T,B,H] f32
    const int*   lens    = (const int*)d_in[1];     // [B]
    const int*   tags    = (const int*)d_in[2];     // [T,B]
    const float* W       = (const float*)d_in[3];   // [K,H]
    const float* bias    = (const float*)d_in[4];   // [K]
    const float* begin   = (const float*)d_in[5];   // [K]
    const float* trans   = (const float*)d_in[6];   // [K,K]
    const float* endt    = (const float*)d_in[7];   // [K]
    float* out = (float*)d_out;

    cudaFuncSetAttribute(emis_gemm, cudaFuncAttributeMaxDynamicSharedMemorySize, 65536);

    emis_gemm<<<M_DIM / 256, 256, 65536>>>(hiddens, W, bias);
    crf_dp<<<B_DIM / 2, 256>>>(lens, tags, trans, begin, endt, out);
}

// round 11
// speedup vs baseline: 1.9026x; 1.0058x over previous
#include <cuda_runtime.h>
#include <cuda_bf16.h>
#include <cstdint>

#define T_DIM 256
#define B_DIM 256
#define H_DIM 512
#define K_DIM 64
#define M_DIM (T_DIM * B_DIM)

// Scratch (device globals; no allocations anywhere)
__device__ float g_em[(size_t)M_DIM * K_DIM];   // emissions [T,B,K] f32
__device__ float g_diff[B_DIM];                 // per-batch forward - gold
__device__ unsigned int g_cnt = 0;              // last-block counter (self-resetting)

__device__ __forceinline__ uint32_t f2bf2(float lo, float hi) {
    uint32_t r;
    asm("cvt.rn.bf16x2.f32 %0, %1, %2;" : "=r"(r) : "f"(hi), "f"(lo));
    return r;
}

// ---------------------------------------------------------------------------
// Kernel 1: emissions GEMM  em[m,k] = sum_h hid[m,h] * W[k,h] + b[k]
// k-PERMUTED fragments: thread tg owns k-cols {4tg..4tg+3} within each
// 16-chunk -> A loads are one LDG.128 per row (was 2x LDG.64): halves L1
// wavefronts. B staged to match: u64 = (W2[8kk+2tg], W2[8kk+2tg+1]).
// Same swizzle; warp = 32 rows x 64 cols; grid 256 = single wave.
// ---------------------------------------------------------------------------
extern __shared__ unsigned long long sB[];   // 8192 u64 = 64 KB dynamic

__global__ __launch_bounds__(256, 2) void emis_gemm(const float* __restrict__ hid,
                                                    const float* __restrict__ W,
                                                    const float* __restrict__ bias) {
    int tid = threadIdx.x;

    // Stage W: u64[n][kk][tg] = bf16x4 of W[n][16kk + 4tg .. +3]
    for (int i = tid; i < (K_DIM * H_DIM) / 4; i += 256) {
        int n  = i >> 7;
        int r  = i & 127;
        int kk = r >> 2;
        int tg = r & 3;
        float4 v = *(const float4*)(W + n * H_DIM + kk * 16 + tg * 4);
        uint32_t wl = f2bf2(v.x, v.y);
        uint32_t wh = f2bf2(v.z, v.w);
        unsigned long long u;
        asm("mov.b64 %0, {%1,%2};" : "=l"(u) : "r"(wl), "r"(wh));
        int g = n & 7, nt = n >> 3;
        int p = nt >> 1, half = nt & 1;
        sB[(kk * 4 + tg) * 64 + (p * 8 + (g ^ (tg << 1))) * 2 + half] = u;
    }
    __syncthreads();

    int warp = tid >> 5;
    int lane = tid & 31;
    int g  = lane >> 2;
    int tg = lane & 3;
    int row0 = blockIdx.x * 256 + warp * 32;

    const float* a0p = hid + (size_t)(row0 + g)      * H_DIM + tg * 4;
    const float* a1p = hid + (size_t)(row0 + g + 8)  * H_DIM + tg * 4;
    const float* a2p = hid + (size_t)(row0 + g + 16) * H_DIM + tg * 4;
    const float* a3p = hid + (size_t)(row0 + g + 24) * H_DIM + tg * 4;

    float acc[16][4];
#pragma unroll
    for (int nt = 0; nt < 16; nt++)
#pragma unroll
        for (int q = 0; q < 4; q++) acc[nt][q] = 0.f;

    // prime A double-buffer: one float4 per row
    float4 v0 = *(const float4*)(a0p);
    float4 v1 = *(const float4*)(a1p);
    float4 v2 = *(const float4*)(a2p);
    float4 v3 = *(const float4*)(a3p);

#pragma unroll 4
    for (int kk = 0; kk < 32; kk++) {
        uint32_t a0 = f2bf2(v0.x, v0.y), a2 = f2bf2(v0.z, v0.w);  // row g   lo/hi
        uint32_t a1 = f2bf2(v1.x, v1.y), a3 = f2bf2(v1.z, v1.w);  // row g+8 lo/hi
        uint32_t c0 = f2bf2(v2.x, v2.y), c2 = f2bf2(v2.z, v2.w);  // row g+16
        uint32_t c1 = f2bf2(v3.x, v3.y), c3 = f2bf2(v3.z, v3.w);  // row g+24
        if (kk < 31) {
            int k0 = (kk + 1) * 16;
            v0 = *(const float4*)(a0p + k0);
            v1 = *(const float4*)(a1p + k0);
            v2 = *(const float4*)(a2p + k0);
            v3 = *(const float4*)(a3p + k0);
        }
        const unsigned long long* rowp = sB + ((kk * 4 + tg) << 6) + (g ^ (tg << 1)) * 2;
#pragma unroll
        for (int p = 0; p < 4; p++) {
            uint4 bb = *(const uint4*)(rowp + p * 16);
            int n0 = 2 * p, n1 = 2 * p + 1;
            asm volatile(
                "mma.sync.aligned.m16n8k16.row.col.f32.bf16.bf16.f32 "
                "{%0,%1,%2,%3}, {%4,%5,%6,%7}, {%8,%9}, {%0,%1,%2,%3};"
                : "+f"(acc[n0][0]), "+f"(acc[n0][1]), "+f"(acc[n0][2]), "+f"(acc[n0][3])
                : "r"(a0), "r"(a1), "r"(a2), "r"(a3), "r"(bb.x), "r"(bb.y));
            asm volatile(
                "mma.sync.aligned.m16n8k16.row.col.f32.bf16.bf16.f32 "
                "{%0,%1,%2,%3}, {%4,%5,%6,%7}, {%8,%9}, {%0,%1,%2,%3};"
                : "+f"(acc[n1][0]), "+f"(acc[n1][1]), "+f"(acc[n1][2]), "+f"(acc[n1][3])
                : "r"(a0), "r"(a1), "r"(a2), "r"(a3), "r"(bb.z), "r"(bb.w));
            asm volatile(
                "mma.sync.aligned.m16n8k16.row.col.f32.bf16.bf16.f32 "
                "{%0,%1,%2,%3}, {%4,%5,%6,%7}, {%8,%9}, {%0,%1,%2,%3};"
                : "+f"(acc[n0 + 8][0]), "+f"(acc[n0 + 8][1]), "+f"(acc[n0 + 8][2]), "+f"(acc[n0 + 8][3])
                : "r"(c0), "r"(c1), "r"(c2), "r"(c3), "r"(bb.x), "r"(bb.y));
            asm volatile(
                "mma.sync.aligned.m16n8k16.row.col.f32.bf16.bf16.f32 "
                "{%0,%1,%2,%3}, {%4,%5,%6,%7}, {%8,%9}, {%0,%1,%2,%3};"
                : "+f"(acc[n1 + 8][0]), "+f"(acc[n1 + 8][1]), "+f"(acc[n1 + 8][2]), "+f"(acc[n1 + 8][3])
                : "r"(c0), "r"(c1), "r"(c2), "r"(c3), "r"(bb.z), "r"(bb.w));
        }
    }

    int r0 = row0 + g;
#pragma unroll
    for (int nt = 0; nt < 8; nt++) {
        int c = nt * 8 + tg * 2;
        float b0v = bias[c], b1v = bias[c + 1];
        float2 o;
        o.x = acc[nt][0] + b0v; o.y = acc[nt][1] + b1v;
        *(float2*)(g_em + (size_t)r0 * K_DIM + c) = o;
        o.x = acc[nt][2] + b0v; o.y = acc[nt][3] + b1v;
        *(float2*)(g_em + (size_t)(r0 + 8) * K_DIM + c) = o;
        o.x = acc[nt + 8][0] + b0v; o.y = acc[nt + 8][1] + b1v;
        *(float2*)(g_em + (size_t)(r0 + 16) * K_DIM + c) = o;
        o.x = acc[nt + 8][2] + b0v; o.y = acc[nt + 8][3] + b1v;
        *(float2*)(g_em + (size_t)(r0 + 24) * K_DIM + c) = o;
    }
}

// ---------------------------------------------------------------------------
// Kernel 2: BIDIRECTIONAL CRF DP + gold + fused final reduction.
// (unchanged from R10: measured 78.3us wall contribution ~22us warm)
// ---------------------------------------------------------------------------
#define FMA2(acc, a, b) \
    asm("fma.rn.f32x2 %0, %1, %2, %3;" : "=l"(acc) : "l"(a), "l"(b), "l"(acc))

__global__ __launch_bounds__(256) void crf_dp(const int* __restrict__ lens,
                                              const int* __restrict__ tags,
                                              const float* __restrict__ trans,
                                              const float* __restrict__ begin,
                                              const float* __restrict__ endt,
                                              float* __restrict__ out) {
    int tid  = threadIdx.x;
    int gid  = tid >> 6;          // 0..3
    int j    = tid & 63;
    int lane = tid & 31;
    int wing = (tid >> 5) & 1;
    int pair = gid >> 1;          // 0,1: batch within block
    int bw   = gid & 1;           // 0 = forward, 1 = backward
    int b    = blockIdx.x * 2 + pair;
    int len  = lens[b];
    int barid   = gid + 1;        // group barrier (64 thr)
    int pairbar = 5 + pair;       // pair barrier (128 thr)

    int mid    = (len - 1) >> 1;
    int nsteps = bw ? (len - 1 - mid) : mid;

    __shared__ __align__(16) float sm_u[4][2][64];
    __shared__ __align__(16) float sm_fin[2][64];
    __shared__ float sm_g[4][2];
    __shared__ float sm_cb[2];

#define GBAR()  asm volatile("bar.sync %0, 64;"  :: "r"(barid)   : "memory")
#define PBAR()  asm volatile("bar.sync %0, 128;" :: "r"(pairbar) : "memory")

    // ---- gold path score (forward groups only) ----
    float goldv = 0.f;
    if (!bw) {
        float gpart = 0.f;
        for (int t = j; t < len; t += 64) {
            int tag = tags[t * B_DIM + b];
            float inc;
            if (t == 0) inc = begin[tag];
            else        inc = trans[tag * K_DIM + tags[(t - 1) * B_DIM + b]];
            inc += g_em[((size_t)t * B_DIM + b) * K_DIM + tag];
            gpart += inc;
        }
#pragma unroll
        for (int o = 16; o; o >>= 1) gpart += __shfl_down_sync(0xffffffffu, gpart, o);
        if (lane == 0) sm_g[gid][wing] = gpart;
        GBAR();
        if (j == 0)
            goldv = sm_g[gid][0] + sm_g[gid][1] + endt[tags[(len - 1) * B_DIM + b]];
    }

    // ---- exp(transition): fwd = row j of E, bwd = column j (row of E^T) ----
    unsigned long long eT2[32];
    if (!bw) {
        const float4* tr4 = (const float4*)(trans + j * K_DIM);
#pragma unroll
        for (int q = 0; q < 16; q++) {
            float4 v = tr4[q];
            float e0 = __expf(v.x), e1 = __expf(v.y);
            float e2 = __expf(v.z), e3 = __expf(v.w);
            asm("mov.b64 %0, {%1,%2};" : "=l"(eT2[2*q])   : "f"(e0), "f"(e1));
            asm("mov.b64 %0, {%1,%2};" : "=l"(eT2[2*q+1]) : "f"(e2), "f"(e3));
        }
    } else {
#pragma unroll
        for (int q = 0; q < 32; q++) {
            float t0 = __expf(trans[(2 * q) * K_DIM + j]);
            float t1 = __expf(trans[(2 * q + 1) * K_DIM + j]);
            asm("mov.b64 %0, {%1,%2};" : "=l"(eT2[q]) : "f"(t0), "f"(t1));
        }
    }

#define CT(k) ({ int _v = bw ? (len - 1 - (k)) : ((k) + 1); \
                 _v = _v < 0 ? 0 : (_v > len - 1 ? len - 1 : _v); _v; })

    // ---- init ----
    float u_reg, C;
    if (!bw) {
        float a00 = begin[0] + g_em[(size_t)b * K_DIM];
        u_reg = __expf(begin[j] + g_em[(size_t)b * K_DIM + j] - a00);
        C = a00;
    } else {
        float e0 = endt[0];
        u_reg = __expf(endt[j] - e0);
        C = e0;
    }

    float xq[2], e0q[2];
    float rawJ[4], raw0[4];
    {
#pragma unroll
        for (int s = 0; s < 4; s++) {
            size_t base = ((size_t)CT(s + 2) * B_DIM + b) * K_DIM;
            rawJ[s] = g_em[base + j];
            raw0[s] = g_em[base];
        }
        size_t b1 = ((size_t)CT(0) * B_DIM + b) * K_DIM;
        size_t b2 = ((size_t)CT(1) * B_DIM + b) * K_DIM;
        float e1j = g_em[b1 + j], e10 = g_em[b1];
        float e2j = g_em[b2 + j], e20 = g_em[b2];
        xq[0] = __expf(e1j - e10); e0q[0] = e10;
        xq[1] = __expf(e2j - e20); e0q[1] = e20;
    }
    sm_u[gid][0][j] = bw ? (u_reg * xq[0]) : u_reg;

    // ---- serial DP: nsteps, ONE named barrier each ----
#pragma unroll 4
    for (int k = 0; k < nsteps; k++) {
        int buf = k & 1, nbuf = buf ^ 1, p = k & 3;
        GBAR();

        const float* ubase = sm_u[gid][buf];
        float v0 = ubase[0];
        float ir;
        asm("rcp.approx.f32 %0, %1;" : "=f"(ir) : "f"(v0));

        const ulonglong2* pp = (const ulonglong2*)ubase;
        unsigned long long acc0 = 0, acc1 = 0, acc2 = 0, acc3 = 0;
#pragma unroll
        for (int q = 0; q < 16; q += 2) {
            ulonglong2 va = pp[q];
            ulonglong2 vb = pp[q + 1];
            FMA2(acc0, va.x, eT2[2*q]);
            FMA2(acc1, va.y, eT2[2*q+1]);
            FMA2(acc2, vb.x, eT2[2*q+2]);
            FMA2(acc3, vb.y, eT2[2*q+3]);
        }
        float s;
        {
            float l0, h0, l1, h1, l2, h2, l3, h3;
            asm("mov.b64 {%0,%1}, %2;" : "=f"(l0), "=f"(h0) : "l"(acc0));
            asm("mov.b64 {%0,%1}, %2;" : "=f"(l1), "=f"(h1) : "l"(acc1));
            asm("mov.b64 {%0,%1}, %2;" : "=f"(l2), "=f"(h2) : "l"(acc2));
            asm("mov.b64 {%0,%1}, %2;" : "=f"(l3), "=f"(h3) : "l"(acc3));
            s = ((l0 + h0) + (l1 + h1)) + ((l2 + h2) + (l3 + h3));
        }
        float un = bw ? (s * ir) : (s * (xq[buf] * ir));
        u_reg = un;
        C += e0q[buf] - __logf(ir);
        sm_u[gid][nbuf][j] = bw ? (un * xq[nbuf]) : un;

        float r0 = raw0[p];
        xq[buf] = __expf(rawJ[p] - r0);
        e0q[buf] = r0;
        size_t base = ((size_t)CT(k + 6) * B_DIM + b) * K_DIM;
        rawJ[p] = g_em[base + j];
        raw0[p] = g_em[base];
    }
#undef CT

    // ---- meet in the middle ----
    if (bw) {
        sm_fin[pair][j] = u_reg;
        if (j == 0) sm_cb[pair] = C;
    }
    PBAR();
    if (!bw) {
        float val = u_reg * sm_fin[pair][j];
#pragma unroll
        for (int o = 16; o; o >>= 1) val += __shfl_down_sync(0xffffffffu, val, o);
        if (lane == 0) sm_g[gid][wing] = val;
        GBAR();
        if (j == 0) {
            float fwd = C + sm_cb[pair] + __logf(sm_g[gid][0] + sm_g[gid][1]);
            g_diff[b] = fwd - goldv;
        }
    }
#undef GBAR
#undef PBAR

    // ---- fused deterministic final reduction (last block) ----
    __syncthreads();
    __shared__ unsigned int s_last;
    if (tid == 0) {
        __threadfence();
        unsigned int old = atomicAdd(&g_cnt, 1u);
        s_last = (old == (unsigned)(gridDim.x - 1)) ? 1u : 0u;
    }
    __syncthreads();
    if (s_last) {
        __shared__ float sr[256];
        if (tid == 0) __threadfence();
        __syncthreads();
        sr[tid] = __ldcg(&g_diff[tid]);
        __syncthreads();
        for (int k = 128; k > 0; k >>= 1) {
            if (tid < k) sr[tid] += sr[tid + k];
            __syncthreads();
        }
        if (tid == 0) {
            out[0] = sr[0];
            g_cnt = 0;   // reset for next graph replay
        }
    }
}

// ---------------------------------------------------------------------------
extern "C" void kernel_launch(void* const* d_in, const int* in_sizes, int n_in,
                              void* d_out, int out_size) {
    const float* hiddens = (const float*)d_in[0];   // [T,B,H] f32
    const int*   lens    = (const int*)d_in[1];     // [B]
    const int*   tags    = (const int*)d_in[2];     // [T,B]
    const float* W       = (const float*)d_in[3];   // [K,H]
    const float* bias    = (const float*)d_in[4];   // [K]
    const float* begin   = (const float*)d_in[5];   // [K]
    const float* trans   = (const float*)d_in[6];   // [K,K]
    const float* endt    = (const float*)d_in[7];   // [K]
    float* out = (float*)d_out;

    cudaFuncSetAttribute(emis_gemm, cudaFuncAttributeMaxDynamicSharedMemorySize, 65536);

    emis_gemm<<<M_DIM / 256, 256, 65536>>>(hiddens, W, bias);
    crf_dp<<<B_DIM / 2, 256>>>(lens, tags, trans, begin, endt, out);
}

// round 12
// speedup vs baseline: 1.9152x; 1.0066x over previous
#include <cuda_runtime.h>
#include <cuda_bf16.h>
#include <cstdint>

#define T_DIM 256
#define B_DIM 256
#define H_DIM 512
#define K_DIM 64
#define M_DIM (T_DIM * B_DIM)

// Scratch (device globals; no allocations anywhere)
__device__ float g_em[(size_t)M_DIM * K_DIM];   // emissions [T,B,K] f32
__device__ float g_diff[B_DIM];                 // per-batch forward - gold
__device__ unsigned int g_cnt = 0;              // last-block counter (self-resetting)

__device__ __forceinline__ uint32_t f2bf2(float lo, float hi) {
    uint32_t r;
    asm("cvt.rn.bf16x2.f32 %0, %1, %2;" : "=r"(r) : "f"(hi), "f"(lo));
    return r;
}

#define CP_ASYNC16(dst32, src) \
    asm volatile("cp.async.cg.shared.global [%0], [%1], 16;" :: "r"(dst32), "l"(src))

// ---------------------------------------------------------------------------
// Kernel 1: emissions GEMM  em[m,k] = sum_h hid[m,h] * W[k,h] + b[k]
// cp.async 3-stage A pipeline (16KB slabs: 256 rows x 16 k-cols f32) ->
// MLP no longer register-bound; .cg bypasses L1. B tile in smem as R11
// (k-permuted u64 fragments). Warp = 32 rows x 64 cols; grid 256 = 1 wave.
// smem: 64KB B + 48KB A = 112KB/block, 2 blocks/SM.
// ---------------------------------------------------------------------------
extern __shared__ char smem_raw[];

__global__ __launch_bounds__(256, 2) void emis_gemm(const float* __restrict__ hid,
                                                    const float* __restrict__ W,
                                                    const float* __restrict__ bias) {
    unsigned long long* sB = (unsigned long long*)smem_raw;
    float* sA = (float*)(smem_raw + 65536);
    int tid = threadIdx.x;

    // ---- stage W: u64[n][kk][tg] = bf16x4 of W[n][16kk + 4tg .. +3] ----
    for (int i = tid; i < (K_DIM * H_DIM) / 4; i += 256) {
        int n  = i >> 7;
        int r  = i & 127;
        int kk = r >> 2;
        int tg = r & 3;
        float4 v = *(const float4*)(W + n * H_DIM + kk * 16 + tg * 4);
        uint32_t wl = f2bf2(v.x, v.y);
        uint32_t wh = f2bf2(v.z, v.w);
        unsigned long long u;
        asm("mov.b64 %0, {%1,%2};" : "=l"(u) : "r"(wl), "r"(wh));
        int g = n & 7, nt = n >> 3;
        int p = nt >> 1, half = nt & 1;
        sB[(kk * 4 + tg) * 64 + (p * 8 + (g ^ (tg << 1))) * 2 + half] = u;
    }

    // ---- cp.async A pipeline setup ----
    int crow = tid >> 2;                 // 0..63
    int cseg = tid & 3;                  // 0..3
    uint32_t sA32 = (uint32_t)__cvta_generic_to_shared(sA);
    const float* gA = hid + (size_t)blockIdx.x * 256 * H_DIM;
    uint32_t dbase0 = sA32 + cseg * 16 + crow * 64;      // + buf*16384 + q*4096
    const float* sbase0 = gA + (size_t)crow * H_DIM + cseg * 4;  // + q*64*H + s*16

#define ISSUE_STAGE(s) do {                                                  \
        int _buf = (s) % 3;                                                  \
        uint32_t _d = dbase0 + _buf * 16384;                                 \
        const float* _s = sbase0 + (s) * 16;                                 \
        CP_ASYNC16(_d,          _s);                                         \
        CP_ASYNC16(_d + 4096,   _s + (size_t)64  * H_DIM);                   \
        CP_ASYNC16(_d + 8192,   _s + (size_t)128 * H_DIM);                   \
        CP_ASYNC16(_d + 12288,  _s + (size_t)192 * H_DIM);                   \
        asm volatile("cp.async.commit_group;");                              \
    } while (0)

    ISSUE_STAGE(0);
    ISSUE_STAGE(1);
    __syncthreads();     // B tile visible; stages 0,1 in flight

    int warp = tid >> 5;
    int lane = tid & 31;
    int g  = lane >> 2;
    int tg = lane & 3;
    int row0 = blockIdx.x * 256 + warp * 32;
    int afrag = warp * 32 * 16 + g * 16 + tg * 4;   // float index; +8 rows = +128

    float acc[16][4];
#pragma unroll
    for (int nt = 0; nt < 16; nt++)
#pragma unroll
        for (int q = 0; q < 4; q++) acc[nt][q] = 0.f;

    for (int kk = 0; kk < 32; kk++) {
        if (kk < 29) { asm volatile("cp.async.wait_group 1;"); }
        else         { asm volatile("cp.async.wait_group 0;"); }
        __syncthreads();                    // stage kk ready; stage kk-1 buffer free
        if (kk + 2 < 32) ISSUE_STAGE(kk + 2);

        const float* abuf = sA + (kk % 3) * 4096 + afrag;
        float4 v0 = *(const float4*)(abuf);
        float4 v1 = *(const float4*)(abuf + 128);
        float4 v2 = *(const float4*)(abuf + 256);
        float4 v3 = *(const float4*)(abuf + 384);

        uint32_t a0 = f2bf2(v0.x, v0.y), a2 = f2bf2(v0.z, v0.w);  // row g
        uint32_t a1 = f2bf2(v1.x, v1.y), a3 = f2bf2(v1.z, v1.w);  // row g+8
        uint32_t c0 = f2bf2(v2.x, v2.y), c2 = f2bf2(v2.z, v2.w);  // row g+16
        uint32_t c1 = f2bf2(v3.x, v3.y), c3 = f2bf2(v3.z, v3.w);  // row g+24

        const unsigned long long* rowp = sB + ((kk * 4 + tg) << 6) + (g ^ (tg << 1)) * 2;
#pragma unroll
        for (int p = 0; p < 4; p++) {
            uint4 bb = *(const uint4*)(rowp + p * 16);
            int n0 = 2 * p, n1 = 2 * p + 1;
            asm volatile(
                "mma.sync.aligned.m16n8k16.row.col.f32.bf16.bf16.f32 "
                "{%0,%1,%2,%3}, {%4,%5,%6,%7}, {%8,%9}, {%0,%1,%2,%3};"
                : "+f"(acc[n0][0]), "+f"(acc[n0][1]), "+f"(acc[n0][2]), "+f"(acc[n0][3])
                : "r"(a0), "r"(a1), "r"(a2), "r"(a3), "r"(bb.x), "r"(bb.y));
            asm volatile(
                "mma.sync.aligned.m16n8k16.row.col.f32.bf16.bf16.f32 "
                "{%0,%1,%2,%3}, {%4,%5,%6,%7}, {%8,%9}, {%0,%1,%2,%3};"
                : "+f"(acc[n1][0]), "+f"(acc[n1][1]), "+f"(acc[n1][2]), "+f"(acc[n1][3])
                : "r"(a0), "r"(a1), "r"(a2), "r"(a3), "r"(bb.z), "r"(bb.w));
            asm volatile(
                "mma.sync.aligned.m16n8k16.row.col.f32.bf16.bf16.f32 "
                "{%0,%1,%2,%3}, {%4,%5,%6,%7}, {%8,%9}, {%0,%1,%2,%3};"
                : "+f"(acc[n0 + 8][0]), "+f"(acc[n0 + 8][1]), "+f"(acc[n0 + 8][2]), "+f"(acc[n0 + 8][3])
                : "r"(c0), "r"(c1), "r"(c2), "r"(c3), "r"(bb.x), "r"(bb.y));
            asm volatile(
                "mma.sync.aligned.m16n8k16.row.col.f32.bf16.bf16.f32 "
                "{%0,%1,%2,%3}, {%4,%5,%6,%7}, {%8,%9}, {%0,%1,%2,%3};"
                : "+f"(acc[n1 + 8][0]), "+f"(acc[n1 + 8][1]), "+f"(acc[n1 + 8][2]), "+f"(acc[n1 + 8][3])
                : "r"(c0), "r"(c1), "r"(c2), "r"(c3), "r"(bb.z), "r"(bb.w));
        }
    }
#undef ISSUE_STAGE

    int r0 = row0 + g;
#pragma unroll
    for (int nt = 0; nt < 8; nt++) {
        int c = nt * 8 + tg * 2;
        float b0v = bias[c], b1v = bias[c + 1];
        float2 o;
        o.x = acc[nt][0] + b0v; o.y = acc[nt][1] + b1v;
        *(float2*)(g_em + (size_t)r0 * K_DIM + c) = o;
        o.x = acc[nt][2] + b0v; o.y = acc[nt][3] + b1v;
        *(float2*)(g_em + (size_t)(r0 + 8) * K_DIM + c) = o;
        o.x = acc[nt + 8][0] + b0v; o.y = acc[nt + 8][1] + b1v;
        *(float2*)(g_em + (size_t)(r0 + 16) * K_DIM + c) = o;
        o.x = acc[nt + 8][2] + b0v; o.y = acc[nt + 8][3] + b1v;
        *(float2*)(g_em + (size_t)(r0 + 24) * K_DIM + c) = o;
    }
}

// ---------------------------------------------------------------------------
// Kernel 2: BIDIRECTIONAL CRF DP + gold + fused final reduction.
// (unchanged from R10/R11 — measured best)
// ---------------------------------------------------------------------------
#define FMA2(acc, a, b) \
    asm("fma.rn.f32x2 %0, %1, %2, %3;" : "=l"(acc) : "l"(a), "l"(b), "l"(acc))

__global__ __launch_bounds__(256) void crf_dp(const int* __restrict__ lens,
                                              const int* __restrict__ tags,
                                              const float* __restrict__ trans,
                                              const float* __restrict__ begin,
                                              const float* __restrict__ endt,
                                              float* __restrict__ out) {
    int tid  = threadIdx.x;
    int gid  = tid >> 6;          // 0..3
    int j    = tid & 63;
    int lane = tid & 31;
    int wing = (tid >> 5) & 1;
    int pair = gid >> 1;          // 0,1: batch within block
    int bw   = gid & 1;           // 0 = forward, 1 = backward
    int b    = blockIdx.x * 2 + pair;
    int len  = lens[b];
    int barid   = gid + 1;
    int pairbar = 5 + pair;

    int mid    = (len - 1) >> 1;
    int nsteps = bw ? (len - 1 - mid) : mid;

    __shared__ __align__(16) float sm_u[4][2][64];
    __shared__ __align__(16) float sm_fin[2][64];
    __shared__ float sm_g[4][2];
    __shared__ float sm_cb[2];

#define GBAR()  asm volatile("bar.sync %0, 64;"  :: "r"(barid)   : "memory")
#define PBAR()  asm volatile("bar.sync %0, 128;" :: "r"(pairbar) : "memory")

    // ---- gold path score (forward groups only) ----
    float goldv = 0.f;
    if (!bw) {
        float gpart = 0.f;
        for (int t = j; t < len; t += 64) {
            int tag = tags[t * B_DIM + b];
            float inc;
            if (t == 0) inc = begin[tag];
            else        inc = trans[tag * K_DIM + tags[(t - 1) * B_DIM + b]];
            inc += g_em[((size_t)t * B_DIM + b) * K_DIM + tag];
            gpart += inc;
        }
#pragma unroll
        for (int o = 16; o; o >>= 1) gpart += __shfl_down_sync(0xffffffffu, gpart, o);
        if (lane == 0) sm_g[gid][wing] = gpart;
        GBAR();
        if (j == 0)
            goldv = sm_g[gid][0] + sm_g[gid][1] + endt[tags[(len - 1) * B_DIM + b]];
    }

    // ---- exp(transition): fwd = row j of E, bwd = column j ----
    unsigned long long eT2[32];
    if (!bw) {
        const float4* tr4 = (const float4*)(trans + j * K_DIM);
#pragma unroll
        for (int q = 0; q < 16; q++) {
            float4 v = tr4[q];
            float e0 = __expf(v.x), e1 = __expf(v.y);
            float e2 = __expf(v.z), e3 = __expf(v.w);
            asm("mov.b64 %0, {%1,%2};" : "=l"(eT2[2*q])   : "f"(e0), "f"(e1));
            asm("mov.b64 %0, {%1,%2};" : "=l"(eT2[2*q+1]) : "f"(e2), "f"(e3));
        }
    } else {
#pragma unroll
        for (int q = 0; q < 32; q++) {
            float t0 = __expf(trans[(2 * q) * K_DIM + j]);
            float t1 = __expf(trans[(2 * q + 1) * K_DIM + j]);
            asm("mov.b64 %0, {%1,%2};" : "=l"(eT2[q]) : "f"(t0), "f"(t1));
        }
    }

#define CT(k) ({ int _v = bw ? (len - 1 - (k)) : ((k) + 1); \
                 _v = _v < 0 ? 0 : (_v > len - 1 ? len - 1 : _v); _v; })

    // ---- init ----
    float u_reg, C;
    if (!bw) {
        float a00 = begin[0] + g_em[(size_t)b * K_DIM];
        u_reg = __expf(begin[j] + g_em[(size_t)b * K_DIM + j] - a00);
        C = a00;
    } else {
        float e0 = endt[0];
        u_reg = __expf(endt[j] - e0);
        C = e0;
    }

    float xq[2], e0q[2];
    float rawJ[4], raw0[4];
    {
#pragma unroll
        for (int s = 0; s < 4; s++) {
            size_t base = ((size_t)CT(s + 2) * B_DIM + b) * K_DIM;
            rawJ[s] = g_em[base + j];
            raw0[s] = g_em[base];
        }
        size_t b1 = ((size_t)CT(0) * B_DIM + b) * K_DIM;
        size_t b2 = ((size_t)CT(1) * B_DIM + b) * K_DIM;
        float e1j = g_em[b1 + j], e10 = g_em[b1];
        float e2j = g_em[b2 + j], e20 = g_em[b2];
        xq[0] = __expf(e1j - e10); e0q[0] = e10;
        xq[1] = __expf(e2j - e20); e0q[1] = e20;
    }
    sm_u[gid][0][j] = bw ? (u_reg * xq[0]) : u_reg;

    // ---- serial DP: nsteps, ONE named barrier each ----
#pragma unroll 4
    for (int k = 0; k < nsteps; k++) {
        int buf = k & 1, nbuf = buf ^ 1, p = k & 3;
        GBAR();

        const float* ubase = sm_u[gid][buf];
        float v0 = ubase[0];
        float ir;
        asm("rcp.approx.f32 %0, %1;" : "=f"(ir) : "f"(v0));

        const ulonglong2* pp = (const ulonglong2*)ubase;
        unsigned long long acc0 = 0, acc1 = 0, acc2 = 0, acc3 = 0;
#pragma unroll
        for (int q = 0; q < 16; q += 2) {
            ulonglong2 va = pp[q];
            ulonglong2 vb = pp[q + 1];
            FMA2(acc0, va.x, eT2[2*q]);
            FMA2(acc1, va.y, eT2[2*q+1]);
            FMA2(acc2, vb.x, eT2[2*q+2]);
            FMA2(acc3, vb.y, eT2[2*q+3]);
        }
        float s;
        {
            float l0, h0, l1, h1, l2, h2, l3, h3;
            asm("mov.b64 {%0,%1}, %2;" : "=f"(l0), "=f"(h0) : "l"(acc0));
            asm("mov.b64 {%0,%1}, %2;" : "=f"(l1), "=f"(h1) : "l"(acc1));
            asm("mov.b64 {%0,%1}, %2;" : "=f"(l2), "=f"(h2) : "l"(acc2));
            asm("mov.b64 {%0,%1}, %2;" : "=f"(l3), "=f"(h3) : "l"(acc3));
            s = ((l0 + h0) + (l1 + h1)) + ((l2 + h2) + (l3 + h3));
        }
        float un = bw ? (s * ir) : (s * (xq[buf] * ir));
        u_reg = un;
        C += e0q[buf] - __logf(ir);
        sm_u[gid][nbuf][j] = bw ? (un * xq[nbuf]) : un;

        float r0 = raw0[p];
        xq[buf] = __expf(rawJ[p] - r0);
        e0q[buf] = r0;
        size_t base = ((size_t)CT(k + 6) * B_DIM + b) * K_DIM;
        rawJ[p] = g_em[base + j];
        raw0[p] = g_em[base];
    }
#undef CT

    // ---- meet in the middle ----
    if (bw) {
        sm_fin[pair][j] = u_reg;
        if (j == 0) sm_cb[pair] = C;
    }
    PBAR();
    if (!bw) {
        float val = u_reg * sm_fin[pair][j];
#pragma unroll
        for (int o = 16; o; o >>= 1) val += __shfl_down_sync(0xffffffffu, val, o);
        if (lane == 0) sm_g[gid][wing] = val;
        GBAR();
        if (j == 0) {
            float fwd = C + sm_cb[pair] + __logf(sm_g[gid][0] + sm_g[gid][1]);
            g_diff[b] = fwd - goldv;
        }
    }
#undef GBAR
#undef PBAR

    // ---- fused deterministic final reduction (last block) ----
    __syncthreads();
    __shared__ unsigned int s_last;
    if (tid == 0) {
        __threadfence();
        unsigned int old = atomicAdd(&g_cnt, 1u);
        s_last = (old == (unsigned)(gridDim.x - 1)) ? 1u : 0u;
    }
    __syncthreads();
    if (s_last) {
        __shared__ float sr[256];
        if (tid == 0) __threadfence();
        __syncthreads();
        sr[tid] = __ldcg(&g_diff[tid]);
        __syncthreads();
        for (int k = 128; k > 0; k >>= 1) {
            if (tid < k) sr[tid] += sr[tid + k];
            __syncthreads();
        }
        if (tid == 0) {
            out[0] = sr[0];
            g_cnt = 0;   // reset for next graph replay
        }
    }
}

// ---------------------------------------------------------------------------
extern "C" void kernel_launch(void* const* d_in, const int* in_sizes, int n_in,
                              void* d_out, int out_size) {
    const float* hiddens = (const float*)d_in[0];   // [T,B,H] f32
    const int*   lens    = (const int*)d_in[1];     // [B]
    const int*   tags    = (const int*)d_in[2];     // [T,B]
    const float* W       = (const float*)d_in[3];   // [K,H]
    const float* bias    = (const float*)d_in[4];   // [K]
    const float* begin   = (const float*)d_in[5];   // [K]
    const float* trans   = (const float*)d_in[6];   // [K,K]
    const float* endt    = (const float*)d_in[7];   // [K]
    float* out = (float*)d_out;

    cudaFuncSetAttribute(emis_gemm, cudaFuncAttributeMaxDynamicSharedMemorySize, 114688);

    emis_gemm<<<M_DIM / 256, 256, 114688>>>(hiddens, W, bias);
    crf_dp<<<B_DIM / 2, 256>>>(lens, tags, trans, begin, endt, out);
}

// round 13
// speedup vs baseline: 1.9433x; 1.0147x over previous
#include <cuda_runtime.h>
#include <cuda_bf16.h>
#include <cstdint>

#define T_DIM 256
#define B_DIM 256
#define H_DIM 512
#define K_DIM 64
#define M_DIM (T_DIM * B_DIM)

// Scratch (device globals; no allocations anywhere)
__device__ float g_em[(size_t)M_DIM * K_DIM];          // emissions [T,B,K] f32
__device__ unsigned long long g_Wsw[8192];             // W bf16, swizzled fragment layout
__device__ float g_diff[B_DIM];                        // per-batch forward - gold
__device__ unsigned int g_cnt = 0;                     // last-block counter (self-reset)

__device__ __forceinline__ uint32_t f2bf2(float lo, float hi) {
    uint32_t r;
    asm("cvt.rn.bf16x2.f32 %0, %1, %2;" : "=r"(r) : "f"(hi), "f"(lo));
    return r;
}

#define CP_ASYNC16(dst32, src) \
    asm volatile("cp.async.cg.shared.global [%0], [%1], 16;" :: "r"(dst32), "l"(src))

// bank permutation for the A slab: bijective on row&7, adjacent rows differ in bit2
__device__ __forceinline__ int XM(int row) {
    return ((((row & 1) << 2) | ((row >> 1) & 3)) << 4);
}

// ---------------------------------------------------------------------------
// Kernel 0: prep W -> global swizzled bf16 fragment layout (u64 per 4 elems)
// Layout identical to the old smem sB: idx = (S*4+tg)*64 + (p*8+(g^(tg<<1)))*2+half
// with n = p*16 + half*8 + g, u64 = bf16x4 of W[n][S*16 + tg*4 .. +3].
// ---------------------------------------------------------------------------
__global__ void prep_w(const float* __restrict__ W) {
    int i = blockIdx.x * 256 + threadIdx.x;     // 0..8191
    int n  = i >> 7;
    int r  = i & 127;
    int kk = r >> 2;       // k16 step S, 0..31
    int tg = r & 3;
    float4 v = *(const float4*)(W + n * H_DIM + kk * 16 + tg * 4);
    uint32_t wl = f2bf2(v.x, v.y);
    uint32_t wh = f2bf2(v.z, v.w);
    unsigned long long u;
    asm("mov.b64 %0, {%1,%2};" : "=l"(u) : "r"(wl), "r"(wh));
    int g = n & 7, nt = n >> 3;
    int p = nt >> 1, half = nt & 1;
    g_Wsw[(kk * 4 + tg) * 64 + (p * 8 + (g ^ (tg << 1))) * 2 + half] = u;
}

// ---------------------------------------------------------------------------
// Kernel 1: emissions GEMM. B fragments from L1-resident g_Wsw (contiguous
// LDG.128). A via cp.async 3-stage ring, warp-contiguous rows (4 lines/instr),
// bank-exact XOR swizzle. MMA core identical to R10/R11 (warp = 32 rows x 64).
// smem = 3 x 32KB = 96KB -> 2 blocks/SM, grid 256 = single wave.
// ---------------------------------------------------------------------------
extern __shared__ char smem_raw[];

__global__ __launch_bounds__(256, 2) void emis_gemm(const float* __restrict__ hid,
                                                    const float* __restrict__ bias) {
    int tid = threadIdx.x;
    uint32_t sA32 = (uint32_t)__cvta_generic_to_shared(smem_raw);
    const float* gA = hid + (size_t)blockIdx.x * 256 * H_DIM;

    // staging map: piece i (0..7): row = i*32 + (tid>>3), pcol = tid&7
    int rowt = tid >> 3;                 // 0..31
    int pcol = tid & 7;
    int pc16x = (pcol * 16) ^ XM(rowt);  // row&7 invariant under +32
    const float* srow = gA + (size_t)rowt * H_DIM + pcol * 4;
    uint32_t drow = sA32 + rowt * 128 + pc16x;

#define ISSUE_STAGE(s) do {                                                   \
        uint32_t _d = drow + ((s) % 3) * 32768;                               \
        const float* _s = srow + (s) * 32;                                    \
        CP_ASYNC16(_d,           _s);                                         \
        CP_ASYNC16(_d + 4096,    _s + (size_t)32  * H_DIM);                   \
        CP_ASYNC16(_d + 8192,    _s + (size_t)64  * H_DIM);                   \
        CP_ASYNC16(_d + 12288,   _s + (size_t)96  * H_DIM);                   \
        CP_ASYNC16(_d + 16384,   _s + (size_t)128 * H_DIM);                   \
        CP_ASYNC16(_d + 20480,   _s + (size_t)160 * H_DIM);                   \
        CP_ASYNC16(_d + 24576,   _s + (size_t)192 * H_DIM);                   \
        CP_ASYNC16(_d + 28672,   _s + (size_t)224 * H_DIM);                   \
        asm volatile("cp.async.commit_group;");                               \
    } while (0)

    ISSUE_STAGE(0);
    ISSUE_STAGE(1);

    int warp = tid >> 5;
    int lane = tid & 31;
    int g  = lane >> 2;
    int tg = lane & 3;
    int row0 = blockIdx.x * 256 + warp * 32;
    int xm2 = XM(g);                     // (warp*32+g+8m)&7 == g&7

    // per-fragment row bases (bytes within a stage)
    int rb0 = (warp * 32 + g)      * 128 + tg * 16;
    int rb1 = (warp * 32 + g + 8)  * 128 + tg * 16;
    int rb2 = (warp * 32 + g + 16) * 128 + tg * 16;
    int rb3 = (warp * 32 + g + 24) * 128 + tg * 16;

    float acc[16][4];
#pragma unroll
    for (int nt = 0; nt < 16; nt++)
#pragma unroll
        for (int q = 0; q < 4; q++) acc[nt][q] = 0.f;

    for (int kk = 0; kk < 16; kk++) {
        if (kk < 15) { asm volatile("cp.async.wait_group 1;"); }
        else         { asm volatile("cp.async.wait_group 0;"); }
        __syncthreads();
        if (kk + 2 < 16) ISSUE_STAGE(kk + 2);

        const char* aptr = smem_raw + (kk % 3) * 32768;
#pragma unroll
        for (int sub = 0; sub < 2; sub++) {
            int so = sub * 64;
            float4 v0 = *(const float4*)(aptr + ((rb0 + so) ^ xm2));
            float4 v1 = *(const float4*)(aptr + ((rb1 + so) ^ xm2));
            float4 v2 = *(const float4*)(aptr + ((rb2 + so) ^ xm2));
            float4 v3 = *(const float4*)(aptr + ((rb3 + so) ^ xm2));

            uint32_t a0 = f2bf2(v0.x, v0.y), a2 = f2bf2(v0.z, v0.w);
            uint32_t a1 = f2bf2(v1.x, v1.y), a3 = f2bf2(v1.z, v1.w);
            uint32_t c0 = f2bf2(v2.x, v2.y), c2 = f2bf2(v2.z, v2.w);
            uint32_t c1 = f2bf2(v3.x, v3.y), c3 = f2bf2(v3.z, v3.w);

            int S = kk * 2 + sub;
            const unsigned long long* rowp =
                g_Wsw + ((S * 4 + tg) << 6) + (g ^ (tg << 1)) * 2;
#pragma unroll
            for (int p = 0; p < 4; p++) {
                uint4 bb = *(const uint4*)(rowp + p * 16);
                int n0 = 2 * p, n1 = 2 * p + 1;
                asm volatile(
                    "mma.sync.aligned.m16n8k16.row.col.f32.bf16.bf16.f32 "
                    "{%0,%1,%2,%3}, {%4,%5,%6,%7}, {%8,%9}, {%0,%1,%2,%3};"
                    : "+f"(acc[n0][0]), "+f"(acc[n0][1]), "+f"(acc[n0][2]), "+f"(acc[n0][3])
                    : "r"(a0), "r"(a1), "r"(a2), "r"(a3), "r"(bb.x), "r"(bb.y));
                asm volatile(
                    "mma.sync.aligned.m16n8k16.row.col.f32.bf16.bf16.f32 "
                    "{%0,%1,%2,%3}, {%4,%5,%6,%7}, {%8,%9}, {%0,%1,%2,%3};"
                    : "+f"(acc[n1][0]), "+f"(acc[n1][1]), "+f"(acc[n1][2]), "+f"(acc[n1][3])
                    : "r"(a0), "r"(a1), "r"(a2), "r"(a3), "r"(bb.z), "r"(bb.w));
                asm volatile(
                    "mma.sync.aligned.m16n8k16.row.col.f32.bf16.bf16.f32 "
                    "{%0,%1,%2,%3}, {%4,%5,%6,%7}, {%8,%9}, {%0,%1,%2,%3};"
                    : "+f"(acc[n0 + 8][0]), "+f"(acc[n0 + 8][1]), "+f"(acc[n0 + 8][2]), "+f"(acc[n0 + 8][3])
                    : "r"(c0), "r"(c1), "r"(c2), "r"(c3), "r"(bb.x), "r"(bb.y));
                asm volatile(
                    "mma.sync.aligned.m16n8k16.row.col.f32.bf16.bf16.f32 "
                    "{%0,%1,%2,%3}, {%4,%5,%6,%7}, {%8,%9}, {%0,%1,%2,%3};"
                    : "+f"(acc[n1 + 8][0]), "+f"(acc[n1 + 8][1]), "+f"(acc[n1 + 8][2]), "+f"(acc[n1 + 8][3])
                    : "r"(c0), "r"(c1), "r"(c2), "r"(c3), "r"(bb.z), "r"(bb.w));
            }
        }
    }
#undef ISSUE_STAGE

    int r0 = row0 + g;
#pragma unroll
    for (int nt = 0; nt < 8; nt++) {
        int c = nt * 8 + tg * 2;
        float b0v = bias[c], b1v = bias[c + 1];
        float2 o;
        o.x = acc[nt][0] + b0v; o.y = acc[nt][1] + b1v;
        *(float2*)(g_em + (size_t)r0 * K_DIM + c) = o;
        o.x = acc[nt][2] + b0v; o.y = acc[nt][3] + b1v;
        *(float2*)(g_em + (size_t)(r0 + 8) * K_DIM + c) = o;
        o.x = acc[nt + 8][0] + b0v; o.y = acc[nt + 8][1] + b1v;
        *(float2*)(g_em + (size_t)(r0 + 16) * K_DIM + c) = o;
        o.x = acc[nt + 8][2] + b0v; o.y = acc[nt + 8][3] + b1v;
        *(float2*)(g_em + (size_t)(r0 + 24) * K_DIM + c) = o;
    }
}

// ---------------------------------------------------------------------------
// Kernel 2: BIDIRECTIONAL CRF DP + gold + fused final reduction. (unchanged)
// ---------------------------------------------------------------------------
#define FMA2(acc, a, b) \
    asm("fma.rn.f32x2 %0, %1, %2, %3;" : "=l"(acc) : "l"(a), "l"(b), "l"(acc))

__global__ __launch_bounds__(256) void crf_dp(const int* __restrict__ lens,
                                              const int* __restrict__ tags,
                                              const float* __restrict__ trans,
                                              const float* __restrict__ begin,
                                              const float* __restrict__ endt,
                                              float* __restrict__ out) {
    int tid  = threadIdx.x;
    int gid  = tid >> 6;
    int j    = tid & 63;
    int lane = tid & 31;
    int wing = (tid >> 5) & 1;
    int pair = gid >> 1;
    int bw   = gid & 1;
    int b    = blockIdx.x * 2 + pair;
    int len  = lens[b];
    int barid   = gid + 1;
    int pairbar = 5 + pair;

    int mid    = (len - 1) >> 1;
    int nsteps = bw ? (len - 1 - mid) : mid;

    __shared__ __align__(16) float sm_u[4][2][64];
    __shared__ __align__(16) float sm_fin[2][64];
    __shared__ float sm_g[4][2];
    __shared__ float sm_cb[2];

#define GBAR()  asm volatile("bar.sync %0, 64;"  :: "r"(barid)   : "memory")
#define PBAR()  asm volatile("bar.sync %0, 128;" :: "r"(pairbar) : "memory")

    float goldv = 0.f;
    if (!bw) {
        float gpart = 0.f;
        for (int t = j; t < len; t += 64) {
            int tag = tags[t * B_DIM + b];
            float inc;
            if (t == 0) inc = begin[tag];
            else        inc = trans[tag * K_DIM + tags[(t - 1) * B_DIM + b]];
            inc += g_em[((size_t)t * B_DIM + b) * K_DIM + tag];
            gpart += inc;
        }
#pragma unroll
        for (int o = 16; o; o >>= 1) gpart += __shfl_down_sync(0xffffffffu, gpart, o);
        if (lane == 0) sm_g[gid][wing] = gpart;
        GBAR();
        if (j == 0)
            goldv = sm_g[gid][0] + sm_g[gid][1] + endt[tags[(len - 1) * B_DIM + b]];
    }

    unsigned long long eT2[32];
    if (!bw) {
        const float4* tr4 = (const float4*)(trans + j * K_DIM);
#pragma unroll
        for (int q = 0; q < 16; q++) {
            float4 v = tr4[q];
            float e0 = __expf(v.x), e1 = __expf(v.y);
            float e2 = __expf(v.z), e3 = __expf(v.w);
            asm("mov.b64 %0, {%1,%2};" : "=l"(eT2[2*q])   : "f"(e0), "f"(e1));
            asm("mov.b64 %0, {%1,%2};" : "=l"(eT2[2*q+1]) : "f"(e2), "f"(e3));
        }
    } else {
#pragma unroll
        for (int q = 0; q < 32; q++) {
            float t0 = __expf(trans[(2 * q) * K_DIM + j]);
            float t1 = __expf(trans[(2 * q + 1) * K_DIM + j]);
            asm("mov.b64 %0, {%1,%2};" : "=l"(eT2[q]) : "f"(t0), "f"(t1));
        }
    }

#define CT(k) ({ int _v = bw ? (len - 1 - (k)) : ((k) + 1); \
                 _v = _v < 0 ? 0 : (_v > len - 1 ? len - 1 : _v); _v; })

    float u_reg, C;
    if (!bw) {
        float a00 = begin[0] + g_em[(size_t)b * K_DIM];
        u_reg = __expf(begin[j] + g_em[(size_t)b * K_DIM + j] - a00);
        C = a00;
    } else {
        float e0 = endt[0];
        u_reg = __expf(endt[j] - e0);
        C = e0;
    }

    float xq[2], e0q[2];
    float rawJ[4], raw0[4];
    {
#pragma unroll
        for (int s = 0; s < 4; s++) {
            size_t base = ((size_t)CT(s + 2) * B_DIM + b) * K_DIM;
            rawJ[s] = g_em[base + j];
            raw0[s] = g_em[base];
        }
        size_t b1 = ((size_t)CT(0) * B_DIM + b) * K_DIM;
        size_t b2 = ((size_t)CT(1) * B_DIM + b) * K_DIM;
        float e1j = g_em[b1 + j], e10 = g_em[b1];
        float e2j = g_em[b2 + j], e20 = g_em[b2];
        xq[0] = __expf(e1j - e10); e0q[0] = e10;
        xq[1] = __expf(e2j - e20); e0q[1] = e20;
    }
    sm_u[gid][0][j] = bw ? (u_reg * xq[0]) : u_reg;

#pragma unroll 4
    for (int k = 0; k < nsteps; k++) {
        int buf = k & 1, nbuf = buf ^ 1, p = k & 3;
        GBAR();

        const float* ubase = sm_u[gid][buf];
        float v0 = ubase[0];
        float ir;
        asm("rcp.approx.f32 %0, %1;" : "=f"(ir) : "f"(v0));

        const ulonglong2* pp = (const ulonglong2*)ubase;
        unsigned long long acc0 = 0, acc1 = 0, acc2 = 0, acc3 = 0;
#pragma unroll
        for (int q = 0; q < 16; q += 2) {
            ulonglong2 va = pp[q];
            ulonglong2 vb = pp[q + 1];
            FMA2(acc0, va.x, eT2[2*q]);
            FMA2(acc1, va.y, eT2[2*q+1]);
            FMA2(acc2, vb.x, eT2[2*q+2]);
            FMA2(acc3, vb.y, eT2[2*q+3]);
        }
        float s;
        {
            float l0, h0, l1, h1, l2, h2, l3, h3;
            asm("mov.b64 {%0,%1}, %2;" : "=f"(l0), "=f"(h0) : "l"(acc0));
            asm("mov.b64 {%0,%1}, %2;" : "=f"(l1), "=f"(h1) : "l"(acc1));
            asm("mov.b64 {%0,%1}, %2;" : "=f"(l2), "=f"(h2) : "l"(acc2));
            asm("mov.b64 {%0,%1}, %2;" : "=f"(l3), "=f"(h3) : "l"(acc3));
            s = ((l0 + h0) + (l1 + h1)) + ((l2 + h2) + (l3 + h3));
        }
        float un = bw ? (s * ir) : (s * (xq[buf] * ir));
        u_reg = un;
        C += e0q[buf] - __logf(ir);
        sm_u[gid][nbuf][j] = bw ? (un * xq[nbuf]) : un;

        float r0 = raw0[p];
        xq[buf] = __expf(rawJ[p] - r0);
        e0q[buf] = r0;
        size_t base = ((size_t)CT(k + 6) * B_DIM + b) * K_DIM;
        rawJ[p] = g_em[base + j];
        raw0[p] = g_em[base];
    }
#undef CT

    if (bw) {
        sm_fin[pair][j] = u_reg;
        if (j == 0) sm_cb[pair] = C;
    }
    PBAR();
    if (!bw) {
        float val = u_reg * sm_fin[pair][j];
#pragma unroll
        for (int o = 16; o; o >>= 1) val += __shfl_down_sync(0xffffffffu, val, o);
        if (lane == 0) sm_g[gid][wing] = val;
        GBAR();
        if (j == 0) {
            float fwd = C + sm_cb[pair] + __logf(sm_g[gid][0] + sm_g[gid][1]);
            g_diff[b] = fwd - goldv;
        }
    }
#undef GBAR
#undef PBAR

    __syncthreads();
    __shared__ unsigned int s_last;
    if (tid == 0) {
        __threadfence();
        unsigned int old = atomicAdd(&g_cnt, 1u);
        s_last = (old == (unsigned)(gridDim.x - 1)) ? 1u : 0u;
    }
    __syncthreads();
    if (s_last) {
        __shared__ float sr[256];
        if (tid == 0) __threadfence();
        __syncthreads();
        sr[tid] = __ldcg(&g_diff[tid]);
        __syncthreads();
        for (int k = 128; k > 0; k >>= 1) {
            if (tid < k) sr[tid] += sr[tid + k];
            __syncthreads();
        }
        if (tid == 0) {
            out[0] = sr[0];
            g_cnt = 0;
        }
    }
}

// ---------------------------------------------------------------------------
extern "C" void kernel_launch(void* const* d_in, const int* in_sizes, int n_in,
                              void* d_out, int out_size) {
    const float* hiddens = (const float*)d_in[0];   // [T,B,H] f32
    const int*   lens    = (const int*)d_in[1];     // [B]
    const int*   tags    = (const int*)d_in[2];     // [T,B]
    const float* W       = (const float*)d_in[3];   // [K,H]
    const float* bias    = (const float*)d_in[4];   // [K]
    const float* begin   = (const float*)d_in[5];   // [K]
    const float* trans   = (const float*)d_in[6];   // [K,K]
    const float* endt    = (const float*)d_in[7];   // [K]
    float* out = (float*)d_out;

    cudaFuncSetAttribute(emis_gemm, cudaFuncAttributeMaxDynamicSharedMemorySize, 98304);

    prep_w<<<32, 256>>>(W);
    emis_gemm<<<M_DIM / 256, 256, 98304>>>(hiddens, bias);
    crf_dp<<<B_DIM / 2, 256>>>(lens, tags, trans, begin, endt, out);
}

// round 14
// speedup vs baseline: 1.9970x; 1.0276x over previous
#include <cuda_runtime.h>
#include <cuda_bf16.h>
#include <cstdint>

#define T_DIM 256
#define B_DIM 256
#define H_DIM 512
#define K_DIM 64
#define M_DIM (T_DIM * B_DIM)

// Scratch (device globals; no allocations anywhere)
__device__ float g_em[(size_t)M_DIM * K_DIM];          // emissions [T,B,K] f32
__device__ unsigned long long g_Wsw[8192];             // W bf16, swizzled fragment layout
__device__ float g_diff[B_DIM];                        // per-batch forward - gold
__device__ unsigned int g_cnt = 0;                     // last-block counter (self-reset)

__device__ __forceinline__ uint32_t f2bf2(float lo, float hi) {
    uint32_t r;
    asm("cvt.rn.bf16x2.f32 %0, %1, %2;" : "=r"(r) : "f"(hi), "f"(lo));
    return r;
}

#define CP_ASYNC16(dst32, src) \
    asm volatile("cp.async.cg.shared.global [%0], [%1], 16;" :: "r"(dst32), "l"(src))

// ---------------------------------------------------------------------------
// Kernel 0: prep W -> global swizzled bf16 fragment layout (u64 per 4 elems)
// idx = (S*4+tg)*64 + (p*8+(g^(tg<<1)))*2 + half, n = p*16+half*8+g,
// u64 = bf16x4 of W[n][S*16 + tg*4 .. +3].
// ---------------------------------------------------------------------------
__global__ void prep_w(const float* __restrict__ W) {
    int i = blockIdx.x * 256 + threadIdx.x;     // 0..8191
    int n  = i >> 7;
    int r  = i & 127;
    int kk = r >> 2;
    int tg = r & 3;
    float4 v = *(const float4*)(W + n * H_DIM + kk * 16 + tg * 4);
    uint32_t wl = f2bf2(v.x, v.y);
    uint32_t wh = f2bf2(v.z, v.w);
    unsigned long long u;
    asm("mov.b64 %0, {%1,%2};" : "=l"(u) : "r"(wl), "r"(wh));
    int g = n & 7, nt = n >> 3;
    int p = nt >> 1, half = nt & 1;
    g_Wsw[(kk * 4 + tg) * 64 + (p * 8 + (g ^ (tg << 1))) * 2 + half] = u;
}

// ---------------------------------------------------------------------------
// Kernel 1: emissions GEMM. DEEP cp.async pipeline: 6 stages x 16KB
// (256 rows x 16 k-cols f32), primed 5, wait_group 4 -> ~80KB/block in
// flight (160KB/SM) -> DRAM/LTS-bound. B fragments from L1-resident g_Wsw.
// MMA core unchanged (warp = 32 rows x 64 cols). Grid 256 = single wave.
// ---------------------------------------------------------------------------
extern __shared__ char smem_raw[];

__global__ __launch_bounds__(256, 2) void emis_gemm(const float* __restrict__ hid,
                                                    const float* __restrict__ bias) {
    int tid = threadIdx.x;
    float* sA = (float*)smem_raw;
    uint32_t sA32 = (uint32_t)__cvta_generic_to_shared(sA);
    const float* gA = hid + (size_t)blockIdx.x * 256 * H_DIM;

    // staging map (R12 shape): thread -> (crow = tid>>2 in 0..63, cseg = tid&3)
    // piece q covers rows crow + 64q; stage s covers k-cols [16s, 16s+16)
    int crow = tid >> 2;
    int cseg = tid & 3;
    uint32_t dbase0 = sA32 + cseg * 16 + crow * 64;              // + buf*16384 + q*4096
    const float* sbase0 = gA + (size_t)crow * H_DIM + cseg * 4;  // + q*64*H + s*16

#define ISSUE_STAGE(s) do {                                                  \
        uint32_t _d = dbase0 + ((s) % 6) * 16384;                            \
        const float* _s = sbase0 + (s) * 16;                                 \
        CP_ASYNC16(_d,          _s);                                         \
        CP_ASYNC16(_d + 4096,   _s + (size_t)64  * H_DIM);                   \
        CP_ASYNC16(_d + 8192,   _s + (size_t)128 * H_DIM);                   \
        CP_ASYNC16(_d + 12288,  _s + (size_t)192 * H_DIM);                   \
        asm volatile("cp.async.commit_group;");                              \
    } while (0)

    ISSUE_STAGE(0);
    ISSUE_STAGE(1);
    ISSUE_STAGE(2);
    ISSUE_STAGE(3);
    ISSUE_STAGE(4);

    int warp = tid >> 5;
    int lane = tid & 31;
    int g  = lane >> 2;
    int tg = lane & 3;
    int row0 = blockIdx.x * 256 + warp * 32;
    int afrag = warp * 512 + g * 16 + tg * 4;   // float index within a stage

    float acc[16][4];
#pragma unroll
    for (int nt = 0; nt < 16; nt++)
#pragma unroll
        for (int q = 0; q < 4; q++) acc[nt][q] = 0.f;

    for (int kk = 0; kk < 32; kk++) {
        if (kk <= 27)      { asm volatile("cp.async.wait_group 4;"); }
        else if (kk == 28) { asm volatile("cp.async.wait_group 3;"); }
        else if (kk == 29) { asm volatile("cp.async.wait_group 2;"); }
        else if (kk == 30) { asm volatile("cp.async.wait_group 1;"); }
        else               { asm volatile("cp.async.wait_group 0;"); }
        __syncthreads();                 // stage kk visible to all; buf kk-1 free
        if (kk + 5 < 32) ISSUE_STAGE(kk + 5);

        const float* abuf = sA + (kk % 6) * 4096 + afrag;
        float4 v0 = *(const float4*)(abuf);          // row g
        float4 v1 = *(const float4*)(abuf + 128);    // row g+8
        float4 v2 = *(const float4*)(abuf + 256);    // row g+16
        float4 v3 = *(const float4*)(abuf + 384);    // row g+24

        uint32_t a0 = f2bf2(v0.x, v0.y), a2 = f2bf2(v0.z, v0.w);
        uint32_t a1 = f2bf2(v1.x, v1.y), a3 = f2bf2(v1.z, v1.w);
        uint32_t c0 = f2bf2(v2.x, v2.y), c2 = f2bf2(v2.z, v2.w);
        uint32_t c1 = f2bf2(v3.x, v3.y), c3 = f2bf2(v3.z, v3.w);

        const unsigned long long* rowp =
            g_Wsw + ((kk * 4 + tg) << 6) + (g ^ (tg << 1)) * 2;
#pragma unroll
        for (int p = 0; p < 4; p++) {
            uint4 bb = *(const uint4*)(rowp + p * 16);
            int n0 = 2 * p, n1 = 2 * p + 1;
            asm volatile(
                "mma.sync.aligned.m16n8k16.row.col.f32.bf16.bf16.f32 "
                "{%0,%1,%2,%3}, {%4,%5,%6,%7}, {%8,%9}, {%0,%1,%2,%3};"
                : "+f"(acc[n0][0]), "+f"(acc[n0][1]), "+f"(acc[n0][2]), "+f"(acc[n0][3])
                : "r"(a0), "r"(a1), "r"(a2), "r"(a3), "r"(bb.x), "r"(bb.y));
            asm volatile(
                "mma.sync.aligned.m16n8k16.row.col.f32.bf16.bf16.f32 "
                "{%0,%1,%2,%3}, {%4,%5,%6,%7}, {%8,%9}, {%0,%1,%2,%3};"
                : "+f"(acc[n1][0]), "+f"(acc[n1][1]), "+f"(acc[n1][2]), "+f"(acc[n1][3])
                : "r"(a0), "r"(a1), "r"(a2), "r"(a3), "r"(bb.z), "r"(bb.w));
            asm volatile(
                "mma.sync.aligned.m16n8k16.row.col.f32.bf16.bf16.f32 "
                "{%0,%1,%2,%3}, {%4,%5,%6,%7}, {%8,%9}, {%0,%1,%2,%3};"
                : "+f"(acc[n0 + 8][0]), "+f"(acc[n0 + 8][1]), "+f"(acc[n0 + 8][2]), "+f"(acc[n0 + 8][3])
                : "r"(c0), "r"(c1), "r"(c2), "r"(c3), "r"(bb.x), "r"(bb.y));
            asm volatile(
                "mma.sync.aligned.m16n8k16.row.col.f32.bf16.bf16.f32 "
                "{%0,%1,%2,%3}, {%4,%5,%6,%7}, {%8,%9}, {%0,%1,%2,%3};"
                : "+f"(acc[n1 + 8][0]), "+f"(acc[n1 + 8][1]), "+f"(acc[n1 + 8][2]), "+f"(acc[n1 + 8][3])
                : "r"(c0), "r"(c1), "r"(c2), "r"(c3), "r"(bb.z), "r"(bb.w));
        }
    }
#undef ISSUE_STAGE

    int r0 = row0 + g;
#pragma unroll
    for (int nt = 0; nt < 8; nt++) {
        int c = nt * 8 + tg * 2;
        float b0v = bias[c], b1v = bias[c + 1];
        float2 o;
        o.x = acc[nt][0] + b0v; o.y = acc[nt][1] + b1v;
        *(float2*)(g_em + (size_t)r0 * K_DIM + c) = o;
        o.x = acc[nt][2] + b0v; o.y = acc[nt][3] + b1v;
        *(float2*)(g_em + (size_t)(r0 + 8) * K_DIM + c) = o;
        o.x = acc[nt + 8][0] + b0v; o.y = acc[nt + 8][1] + b1v;
        *(float2*)(g_em + (size_t)(r0 + 16) * K_DIM + c) = o;
        o.x = acc[nt + 8][2] + b0v; o.y = acc[nt + 8][3] + b1v;
        *(float2*)(g_em + (size_t)(r0 + 24) * K_DIM + c) = o;
    }
}

// ---------------------------------------------------------------------------
// Kernel 2: BIDIRECTIONAL CRF DP + gold + fused final reduction. (unchanged)
// ---------------------------------------------------------------------------
#define FMA2(acc, a, b) \
    asm("fma.rn.f32x2 %0, %1, %2, %3;" : "=l"(acc) : "l"(a), "l"(b), "l"(acc))

__global__ __launch_bounds__(256) void crf_dp(const int* __restrict__ lens,
                                              const int* __restrict__ tags,
                                              const float* __restrict__ trans,
                                              const float* __restrict__ begin,
                                              const float* __restrict__ endt,
                                              float* __restrict__ out) {
    int tid  = threadIdx.x;
    int gid  = tid >> 6;
    int j    = tid & 63;
    int lane = tid & 31;
    int wing = (tid >> 5) & 1;
    int pair = gid >> 1;
    int bw   = gid & 1;
    int b    = blockIdx.x * 2 + pair;
    int len  = lens[b];
    int barid   = gid + 1;
    int pairbar = 5 + pair;

    int mid    = (len - 1) >> 1;
    int nsteps = bw ? (len - 1 - mid) : mid;

    __shared__ __align__(16) float sm_u[4][2][64];
    __shared__ __align__(16) float sm_fin[2][64];
    __shared__ float sm_g[4][2];
    __shared__ float sm_cb[2];

#define GBAR()  asm volatile("bar.sync %0, 64;"  :: "r"(barid)   : "memory")
#define PBAR()  asm volatile("bar.sync %0, 128;" :: "r"(pairbar) : "memory")

    float goldv = 0.f;
    if (!bw) {
        float gpart = 0.f;
        for (int t = j; t < len; t += 64) {
            int tag = tags[t * B_DIM + b];
            float inc;
            if (t == 0) inc = begin[tag];
            else        inc = trans[tag * K_DIM + tags[(t - 1) * B_DIM + b]];
            inc += g_em[((size_t)t * B_DIM + b) * K_DIM + tag];
            gpart += inc;
        }
#pragma unroll
        for (int o = 16; o; o >>= 1) gpart += __shfl_down_sync(0xffffffffu, gpart, o);
        if (lane == 0) sm_g[gid][wing] = gpart;
        GBAR();
        if (j == 0)
            goldv = sm_g[gid][0] + sm_g[gid][1] + endt[tags[(len - 1) * B_DIM + b]];
    }

    unsigned long long eT2[32];
    if (!bw) {
        const float4* tr4 = (const float4*)(trans + j * K_DIM);
#pragma unroll
        for (int q = 0; q < 16; q++) {
            float4 v = tr4[q];
            float e0 = __expf(v.x), e1 = __expf(v.y);
            float e2 = __expf(v.z), e3 = __expf(v.w);
            asm("mov.b64 %0, {%1,%2};" : "=l"(eT2[2*q])   : "f"(e0), "f"(e1));
            asm("mov.b64 %0, {%1,%2};" : "=l"(eT2[2*q+1]) : "f"(e2), "f"(e3));
        }
    } else {
#pragma unroll
        for (int q = 0; q < 32; q++) {
            float t0 = __expf(trans[(2 * q) * K_DIM + j]);
            float t1 = __expf(trans[(2 * q + 1) * K_DIM + j]);
            asm("mov.b64 %0, {%1,%2};" : "=l"(eT2[q]) : "f"(t0), "f"(t1));
        }
    }

#define CT(k) ({ int _v = bw ? (len - 1 - (k)) : ((k) + 1); \
                 _v = _v < 0 ? 0 : (_v > len - 1 ? len - 1 : _v); _v; })

    float u_reg, C;
    if (!bw) {
        float a00 = begin[0] + g_em[(size_t)b * K_DIM];
        u_reg = __expf(begin[j] + g_em[(size_t)b * K_DIM + j] - a00);
        C = a00;
    } else {
        float e0 = endt[0];
        u_reg = __expf(endt[j] - e0);
        C = e0;
    }

    float xq[2], e0q[2];
    float rawJ[4], raw0[4];
    {
#pragma unroll
        for (int s = 0; s < 4; s++) {
            size_t base = ((size_t)CT(s + 2) * B_DIM + b) * K_DIM;
            rawJ[s] = g_em[base + j];
            raw0[s] = g_em[base];
        }
        size_t b1 = ((size_t)CT(0) * B_DIM + b) * K_DIM;
        size_t b2 = ((size_t)CT(1) * B_DIM + b) * K_DIM;
        float e1j = g_em[b1 + j], e10 = g_em[b1];
        float e2j = g_em[b2 + j], e20 = g_em[b2];
        xq[0] = __expf(e1j - e10); e0q[0] = e10;
        xq[1] = __expf(e2j - e20); e0q[1] = e20;
    }
    sm_u[gid][0][j] = bw ? (u_reg * xq[0]) : u_reg;

#pragma unroll 4
    for (int k = 0; k < nsteps; k++) {
        int buf = k & 1, nbuf = buf ^ 1, p = k & 3;
        GBAR();

        const float* ubase = sm_u[gid][buf];
        float v0 = ubase[0];
        float ir;
        asm("rcp.approx.f32 %0, %1;" : "=f"(ir) : "f"(v0));

        const ulonglong2* pp = (const ulonglong2*)ubase;
        unsigned long long acc0 = 0, acc1 = 0, acc2 = 0, acc3 = 0;
#pragma unroll
        for (int q = 0; q < 16; q += 2) {
            ulonglong2 va = pp[q];
            ulonglong2 vb = pp[q + 1];
            FMA2(acc0, va.x, eT2[2*q]);
            FMA2(acc1, va.y, eT2[2*q+1]);
            FMA2(acc2, vb.x, eT2[2*q+2]);
            FMA2(acc3, vb.y, eT2[2*q+3]);
        }
        float s;
        {
            float l0, h0, l1, h1, l2, h2, l3, h3;
            asm("mov.b64 {%0,%1}, %2;" : "=f"(l0), "=f"(h0) : "l"(acc0));
            asm("mov.b64 {%0,%1}, %2;" : "=f"(l1), "=f"(h1) : "l"(acc1));
            asm("mov.b64 {%0,%1}, %2;" : "=f"(l2), "=f"(h2) : "l"(acc2));
            asm("mov.b64 {%0,%1}, %2;" : "=f"(l3), "=f"(h3) : "l"(acc3));
            s = ((l0 + h0) + (l1 + h1)) + ((l2 + h2) + (l3 + h3));
        }
        float un = bw ? (s * ir) : (s * (xq[buf] * ir));
        u_reg = un;
        C += e0q[buf] - __logf(ir);
        sm_u[gid][nbuf][j] = bw ? (un * xq[nbuf]) : un;

        float r0 = raw0[p];
        xq[buf] = __expf(rawJ[p] - r0);
        e0q[buf] = r0;
        size_t base = ((size_t)CT(k + 6) * B_DIM + b) * K_DIM;
        rawJ[p] = g_em[base + j];
        raw0[p] = g_em[base];
    }
#undef CT

    if (bw) {
        sm_fin[pair][j] = u_reg;
        if (j == 0) sm_cb[pair] = C;
    }
    PBAR();
    if (!bw) {
        float val = u_reg * sm_fin[pair][j];
#pragma unroll
        for (int o = 16; o; o >>= 1) val += __shfl_down_sync(0xffffffffu, val, o);
        if (lane == 0) sm_g[gid][wing] = val;
        GBAR();
        if (j == 0) {
            float fwd = C + sm_cb[pair] + __logf(sm_g[gid][0] + sm_g[gid][1]);
            g_diff[b] = fwd - goldv;
        }
    }
#undef GBAR
#undef PBAR

    __syncthreads();
    __shared__ unsigned int s_last;
    if (tid == 0) {
        __threadfence();
        unsigned int old = atomicAdd(&g_cnt, 1u);
        s_last = (old == (unsigned)(gridDim.x - 1)) ? 1u : 0u;
    }
    __syncthreads();
    if (s_last) {
        __shared__ float sr[256];
        if (tid == 0) __threadfence();
        __syncthreads();
        sr[tid] = __ldcg(&g_diff[tid]);
        __syncthreads();
        for (int k = 128; k > 0; k >>= 1) {
            if (tid < k) sr[tid] += sr[tid + k];
            __syncthreads();
        }
        if (tid == 0) {
            out[0] = sr[0];
            g_cnt = 0;
        }
    }
}

// ---------------------------------------------------------------------------
extern "C" void kernel_launch(void* const* d_in, const int* in_sizes, int n_in,
                              void* d_out, int out_size) {
    const float* hiddens = (const float*)d_in[0];   // [T,B,H] f32
    const int*   lens    = (const int*)d_in[1];     // [B]
    const int*   tags    = (const int*)d_in[2];     // [T,B]
    const float* W       = (const float*)d_in[3];   // [K,H]
    const float* bias    = (const float*)d_in[4];   // [K]
    const float* begin   = (const float*)d_in[5];   // [K]
    const float* trans   = (const float*)d_in[6];   // [K,K]
    const float* endt    = (const float*)d_in[7];   // [K]
    float* out = (float*)d_out;

    cudaFuncSetAttribute(emis_gemm, cudaFuncAttributeMaxDynamicSharedMemorySize, 98304);

    prep_w<<<32, 256>>>(W);
    emis_gemm<<<M_DIM / 256, 256, 98304>>>(hiddens, bias);
    crf_dp<<<B_DIM / 2, 256>>>(lens, tags, trans, begin, endt, out);
}